// round 14
// baseline (speedup 1.0000x reference)
#include <cuda_runtime.h>
#include <cuda.h>
#include <cuda_fp16.h>
#include <mma.h>
#include <cstdint>
#include <cstddef>

// Problem dims
#define B_SZ   65536
#define F_DIM  1024
#define H_N    16
#define D_H    64
#define NQKV   3072
#define OUT_N  1024
#define K_DIM  1024

#if defined(__CUDA_ARCH_FEAT_SM103_ALL) || defined(__CUDA_ARCH_FEAT_SM100_ALL)
#define HAS_TCGEN05 1
#else
#define HAS_TCGEN05 0
#endif

// ---------------------------------------------------------------------------
// Scratch (allocation-free: __device__ globals). 1KB-aligned for TMA.
// ---------------------------------------------------------------------------
__device__ __align__(1024) __half g_xh  [(size_t)B_SZ * F_DIM];
__device__ __align__(1024) __half g_wqkv[(size_t)NQKV * K_DIM];
__device__ __align__(1024) __half g_wf  [(size_t)OUT_N * K_DIM];
__device__ __align__(1024) __half g_qkv [(size_t)B_SZ * NQKV];
__device__ __align__(1024) __half g_c   [(size_t)B_SZ * F_DIM];

// ---------------------------------------------------------------------------
// PTX helpers
// ---------------------------------------------------------------------------
__device__ __forceinline__ uint32_t smem_u32(const void* p) {
    return (uint32_t)__cvta_generic_to_shared(p);
}
__device__ __forceinline__ uint32_t ctarank() {
    uint32_t r;
    asm("mov.u32 %0, %%cluster_ctarank;" : "=r"(r));
    return r;
}
__device__ __forceinline__ void cp_async16(uint32_t s, const void* g) {
    asm volatile("cp.async.cg.shared.global [%0], [%1], 16;\n" ::"r"(s), "l"(g));
}
__device__ __forceinline__ void mbar_init(uint64_t* b, uint32_t cnt) {
    asm volatile("mbarrier.init.shared.b64 [%0], %1;" ::"r"(smem_u32(b)), "r"(cnt) : "memory");
}
__device__ __forceinline__ void mbar_arrive(uint64_t* b) {
    asm volatile("mbarrier.arrive.shared.b64 _, [%0];" ::"r"(smem_u32(b)) : "memory");
}
__device__ __forceinline__ void mbar_wait(uint64_t* b, uint32_t parity) {
    uint32_t addr = smem_u32(b);
    asm volatile(
        "{\n\t"
        ".reg .pred P1;\n\t"
        "WAIT_LOOP_%=:\n\t"
        "mbarrier.try_wait.parity.acquire.cta.shared::cta.b64 P1, [%0], %1, 0x989680;\n\t"
        "@P1 bra.uni WAIT_DONE_%=;\n\t"
        "bra.uni WAIT_LOOP_%=;\n\t"
        "WAIT_DONE_%=:\n\t"
        "}"
        ::"r"(addr), "r"(parity) : "memory");
}
#if HAS_TCGEN05
__device__ __forceinline__ void tc_commit(uint64_t* b) {
    asm volatile(
        "tcgen05.commit.cta_group::1.mbarrier::arrive::one.shared::cluster.b64 [%0];"
        ::"r"(smem_u32(b)) : "memory");
}
__device__ __forceinline__ void tc_commit_mc(uint64_t* b, uint16_t mask) {
    asm volatile(
        "tcgen05.commit.cta_group::1.mbarrier::arrive::one.shared::cluster.multicast::cluster.b64 [%0], %1;"
        ::"r"(smem_u32(b)), "h"(mask) : "memory");
}
__device__ __forceinline__ void mbar_expect_tx(uint64_t* b, uint32_t bytes) {
    asm volatile("mbarrier.arrive.expect_tx.shared.b64 _, [%0], %1;"
                 ::"r"(smem_u32(b)), "r"(bytes) : "memory");
}
__device__ __forceinline__ void tma_2d(uint32_t smem, const CUtensorMap* tm,
                                       int c0, int c1, uint32_t mbar) {
    asm volatile(
        "cp.async.bulk.tensor.2d.shared::cta.global.tile.mbarrier::complete_tx::bytes "
        "[%0], [%1, {%2, %3}], [%4];"
        ::"r"(smem), "l"(tm), "r"(c0), "r"(c1), "r"(mbar) : "memory");
}
__device__ __forceinline__ void tma_2d_mc(uint32_t smem, const CUtensorMap* tm,
                                          int c0, int c1, uint32_t mbar,
                                          uint16_t mask) {
    asm volatile(
        "cp.async.bulk.tensor.2d.shared::cluster.global.tile.mbarrier::complete_tx::bytes.multicast::cluster "
        "[%0], [%1, {%2, %3}], [%4], %5;"
        ::"r"(smem), "l"(tm), "r"(c0), "r"(c1), "r"(mbar), "h"(mask) : "memory");
}
// SW64 K-major smem descriptor: layout=4, version=1, SBO=32, LBO=1
// (SW64 atom = 8 rows x 64B; BK=32 f16 rows are 64B wide.)
__device__ __forceinline__ uint64_t make_desc64(uint32_t addr) {
    constexpr uint64_t BASE =
        (uint64_t(4) << 61) | (uint64_t(1) << 46) | (uint64_t(32) << 32) | (uint64_t(1) << 16);
    return BASE | ((uint64_t)(addr >> 4) & 0x3FFF);
}
__device__ __forceinline__ void mma_f16_ss(uint32_t d, uint64_t a, uint64_t b,
                                           uint32_t idesc, uint32_t en) {
    asm volatile(
        "{\n\t"
        ".reg .pred p;\n\t"
        "setp.ne.u32 p, %5, 0;\n\t"
        "tcgen05.mma.cta_group::1.kind::f16 [%0], %1, %2, %3, {%4, %4, %4, %4}, p;\n\t"
        "}"
        ::"r"(d), "l"(a), "l"(b), "r"(idesc), "r"(0u), "r"(en) : "memory");
}
__device__ __forceinline__ void tmem_ld_x32(uint32_t* r, uint32_t tmem_addr) {
    asm volatile(
        "tcgen05.ld.sync.aligned.32x32b.x32.b32 "
        "{%0, %1, %2, %3, %4, %5, %6, %7, "
        " %8, %9, %10, %11, %12, %13, %14, %15, "
        " %16, %17, %18, %19, %20, %21, %22, %23, "
        " %24, %25, %26, %27, %28, %29, %30, %31}, [%32];"
        : "=r"(r[0]), "=r"(r[1]), "=r"(r[2]), "=r"(r[3]),
          "=r"(r[4]), "=r"(r[5]), "=r"(r[6]), "=r"(r[7]),
          "=r"(r[8]), "=r"(r[9]), "=r"(r[10]), "=r"(r[11]),
          "=r"(r[12]), "=r"(r[13]), "=r"(r[14]), "=r"(r[15]),
          "=r"(r[16]), "=r"(r[17]), "=r"(r[18]), "=r"(r[19]),
          "=r"(r[20]), "=r"(r[21]), "=r"(r[22]), "=r"(r[23]),
          "=r"(r[24]), "=r"(r[25]), "=r"(r[26]), "=r"(r[27]),
          "=r"(r[28]), "=r"(r[29]), "=r"(r[30]), "=r"(r[31])
        : "r"(tmem_addr));
}
#endif  // HAS_TCGEN05

// ---------------------------------------------------------------------------
// Converters
// ---------------------------------------------------------------------------
__global__ void convert_x_kernel(const float4* __restrict__ x) {
    const size_t n4 = (size_t)B_SZ * F_DIM / 4;
    int2* out = reinterpret_cast<int2*>(g_xh);
    for (size_t i = (size_t)blockIdx.x * blockDim.x + threadIdx.x; i < n4;
         i += (size_t)gridDim.x * blockDim.x) {
        float4 v = __ldcs(x + i);
        __half2 h0 = __floats2half2_rn(v.x, v.y);
        __half2 h1 = __floats2half2_rn(v.z, v.w);
        int2 pk;
        pk.x = *reinterpret_cast<int*>(&h0);
        pk.y = *reinterpret_cast<int*>(&h1);
        __stcs(out + i, pk);
    }
}

// Coalesced tiled transpose: W[H][F][D] -> g_wqkv[n][f], n = which*1024+h*64+d.
__global__ void convert_wqkv_kernel(const float* __restrict__ Wq,
                                    const float* __restrict__ Wk,
                                    const float* __restrict__ Wv) {
    __shared__ float tile[32][33];
    const int which = blockIdx.z >> 4;
    const int h = blockIdx.z & 15;
    const int f0 = blockIdx.x * 32;
    const int d0 = blockIdx.y * 32;
    const float* W = (which == 0) ? Wq : ((which == 1) ? Wk : Wv);
    const float* src = W + ((size_t)h * F_DIM) * D_H;   // [F][D]

    const int tx = threadIdx.x;
    const int ty = threadIdx.y;
#pragma unroll
    for (int r = 0; r < 4; r++) {
        int f = f0 + ty + r * 8;
        int d = d0 + tx;
        if (d < D_H) tile[ty + r * 8][tx] = src[(size_t)f * D_H + d];
    }
    __syncthreads();
#pragma unroll
    for (int r = 0; r < 4; r++) {
        int d = d0 + ty + r * 8;
        int f = f0 + tx;
        if (d < D_H) {
            int n = which * 1024 + h * 64 + d;
            g_wqkv[(size_t)n * K_DIM + f] = __float2half(tile[tx][ty + r * 8]);
        }
    }
}

// Coalesced tiled transpose: Wf[K][N] -> g_wf[n][k].
__global__ void convert_wf_kernel(const float* __restrict__ Wf) {
    __shared__ float tile[32][33];
    const int k0 = blockIdx.x * 32;
    const int n0 = blockIdx.y * 32;
    const int tx = threadIdx.x;
    const int ty = threadIdx.y;
#pragma unroll
    for (int r = 0; r < 4; r++) {
        int k = k0 + ty + r * 8;
        tile[ty + r * 8][tx] = Wf[(size_t)k * OUT_N + n0 + tx];
    }
    __syncthreads();
#pragma unroll
    for (int r = 0; r < 4; r++) {
        int n = n0 + ty + r * 8;
        g_wf[(size_t)n * K_DIM + k0 + tx] = __float2half(tile[tx][ty + r * 8]);
    }
}

// ---------------------------------------------------------------------------
// Persistent tcgen05 GEMM, cluster-2 with B multicast, N=256 dispatches.
// DEEP PIPELINE: BK=32 (SW64 tiles), 6 stages of 32KB.
// Stage layout: A0 [0,8K), A1 [8K,16K), B [16K,32K) (own mc half at
// +rank*8K; partner's multicast fills the other half).
// ---------------------------------------------------------------------------
#define STAGES 6
#define STAGE_BYTES 32768
#define SMEM_DYN (STAGES * STAGE_BYTES + 1024)
#define KT 32                      // 1024 / 32
#define NTHREADS 512               // 16 warps

// idesc: dtype=F32(1<<4), atype=btype=F16(0), N=256 -> 32<<17, M=128 -> 8<<24
#define IDESC_F16_N256 ((1u << 4) | (32u << 17) | (8u << 24))

template <int N_DIM, bool OUT_HALF, bool BIAS>
__global__ __launch_bounds__(NTHREADS, 1) __cluster_dims__(2, 1, 1)
void tc_gemm(const __grid_constant__ CUtensorMap tmA,
             const __grid_constant__ CUtensorMap tmB,
             const __half* __restrict__ A, const __half* __restrict__ Bw,
             __half* __restrict__ Ch, float* __restrict__ Cf,
             const float* __restrict__ bias, int numSuper, int superN) {
    extern __shared__ __align__(16) char dsm[];
    char* tiles = (char*)(((uintptr_t)dsm + 1023) & ~(uintptr_t)1023);

    const int tid = threadIdx.x;
    const int warp = tid >> 5;
    const int lane = tid & 31;
    const int C = gridDim.x >> 1;        // clusters
    const int cid = blockIdx.x >> 1;
    const int rank = (int)ctarank();     // 0 or 1 within cluster

#if HAS_TCGEN05
    __shared__ __align__(8) uint64_t bar_full[STAGES];
    __shared__ __align__(8) uint64_t bar_empty[STAGES];
    __shared__ __align__(8) uint64_t bar_done;
    __shared__ __align__(8) uint64_t bar_free;
    __shared__ uint32_t s_tmem;

    if (warp == 0) {
        asm volatile(
            "tcgen05.alloc.cta_group::1.sync.aligned.shared::cta.b32 [%0], %1;"
            ::"r"(smem_u32(&s_tmem)), "r"(512) : "memory");
    }
    if (tid == 0) {
        for (int s = 0; s < STAGES; s++) {
            mbar_init(&bar_full[s], 1);
            mbar_init(&bar_empty[s], 2);   // commits from BOTH cluster CTAs
        }
        mbar_init(&bar_done, 1);
        mbar_init(&bar_free, 8);
        asm volatile("fence.proxy.async.shared::cta;" ::: "memory");
    }
    __syncthreads();
    // All mbarriers must be cluster-visible before any multicast TMA / commit.
    asm volatile("barrier.cluster.arrive.aligned;" ::: "memory");
    asm volatile("barrier.cluster.wait.aligned;" ::: "memory");
    const uint32_t tmem = s_tmem;

    if (tid == 0) {
        // ------------------ producer: single thread, TMA ------------------
        asm volatile("prefetch.tensormap [%0];" ::"l"(&tmA));
        asm volatile("prefetch.tensormap [%0];" ::"l"(&tmB));
        int s = 0, ph = 1;  // fresh-barrier: parity-1 wait passes immediately
        for (int t = cid; t < numSuper; t += C) {
            const int tileM = (t / superN) * 512 + rank * 256;
            const int tileN = (t % superN) * 256;
            for (int kt = 0; kt < KT; kt++) {
                mbar_wait(&bar_empty[s], (uint32_t)ph);
                const uint32_t st = smem_u32(tiles + s * STAGE_BYTES);
                const uint32_t mb = smem_u32(&bar_full[s]);
                mbar_expect_tx(&bar_full[s], STAGE_BYTES);
                // own A halves (unicast, own barrier)
                tma_2d(st,        &tmA, kt * 32, tileM,       mb);
                tma_2d(st + 8192, &tmA, kt * 32, tileM + 128, mb);
                // one B box, multicast to both cluster CTAs
                tma_2d_mc(st + 16384 + rank * 8192, &tmB, kt * 32,
                          tileN + rank * 128, mb, (uint16_t)0x3);
                if (++s == STAGES) { s = 0; ph ^= 1; }
            }
        }
    } else if (warp == 4 && lane == 0) {
        // ------------------ MMA issue: single thread ------------------
        int s = 0, ph = 0, ti = 0;
        for (int t = cid; t < numSuper; t += C) {
            if (ti >= 1) {
                mbar_wait(&bar_free, (uint32_t)((ti - 1) & 1));
                asm volatile("tcgen05.fence::after_thread_sync;" ::: "memory");
            }
            for (int kt = 0; kt < KT; kt++) {
                mbar_wait(&bar_full[s], (uint32_t)ph);
                char* st = tiles + s * STAGE_BYTES;
                uint64_t a0 = make_desc64(smem_u32(st));
                uint64_t a1 = make_desc64(smem_u32(st + 8192));
                uint64_t b0 = make_desc64(smem_u32(st + 16384));  // 256 rows
#pragma unroll
                for (int ks = 0; ks < 2; ks++) {
                    uint32_t en = (kt == 0 && ks == 0) ? 0u : 1u;
                    uint64_t ko = (uint64_t)(ks * 2);  // 32 bytes per K-step
                    mma_f16_ss(tmem + 0,   a0 + ko, b0 + ko, IDESC_F16_N256, en);
                    mma_f16_ss(tmem + 256, a1 + ko, b0 + ko, IDESC_F16_N256, en);
                }
                // release the stage in BOTH cluster CTAs (B box is shared)
                tc_commit_mc(&bar_empty[s], (uint16_t)0x3);
                if (++s == STAGES) { s = 0; ph ^= 1; }
            }
            tc_commit(&bar_done);
            ti++;
        }
    } else if (warp >= 8) {
        // ------------- epilogue: warps 8-15, subpartition = warp&3 -------------
        const int mhalf = (warp >> 2) - 2;          // warps 8-11 -> 0, 12-15 -> 1
        const int subp = warp & 3;                  // hardware TMEM lane group
        int ti = 0;
        for (int t = cid; t < numSuper; t += C) {
            const size_t tileM = (size_t)(t / superN) * 512 + rank * 256;
            const int tileN = (t % superN) * 256;
            mbar_wait(&bar_done, (uint32_t)(ti & 1));
            asm volatile("tcgen05.fence::after_thread_sync;" ::: "memory");
            const size_t grow = tileM + mhalf * 128 + subp * 32 + lane;
#pragma unroll
            for (int nb = 0; nb < 8; nb += 2) {
                uint32_t r0[32], r1[32];
                tmem_ld_x32(r0, tmem + mhalf * 256 + nb * 32);
                tmem_ld_x32(r1, tmem + mhalf * 256 + nb * 32 + 32);
                asm volatile("tcgen05.wait::ld.sync.aligned;" ::: "memory");
#pragma unroll
                for (int half2i = 0; half2i < 2; half2i++) {
                    uint32_t* r = half2i ? r1 : r0;
                    const int gc0 = tileN + (nb + half2i) * 32;
                    if (OUT_HALF) {
                        __half2 h2[16];
#pragma unroll
                        for (int i = 0; i < 16; i++)
                            h2[i] = __floats2half2_rn(__uint_as_float(r[2 * i]),
                                                      __uint_as_float(r[2 * i + 1]));
                        int4* dst = reinterpret_cast<int4*>(Ch + grow * N_DIM + gc0);
#pragma unroll
                        for (int i = 0; i < 4; i++)
                            __stcs(dst + i, reinterpret_cast<int4*>(h2)[i]);
                    } else {
                        float4* dst = reinterpret_cast<float4*>(Cf + grow * N_DIM + gc0);
#pragma unroll
                        for (int i = 0; i < 8; i++) {
                            float4 v;
                            v.x = __uint_as_float(r[4 * i + 0]) + (BIAS ? bias[gc0 + 4 * i + 0] : 0.0f);
                            v.y = __uint_as_float(r[4 * i + 1]) + (BIAS ? bias[gc0 + 4 * i + 1] : 0.0f);
                            v.z = __uint_as_float(r[4 * i + 2]) + (BIAS ? bias[gc0 + 4 * i + 2] : 0.0f);
                            v.w = __uint_as_float(r[4 * i + 3]) + (BIAS ? bias[gc0 + 4 * i + 3] : 0.0f);
                            __stcs(dst + i, v);
                        }
                    }
                }
            }
            asm volatile("tcgen05.fence::before_thread_sync;" ::: "memory");
            if (lane == 0) mbar_arrive(&bar_free);
            ti++;
        }
    }

    __syncthreads();
    // No CTA may exit while another CTA's multicast could still target it.
    asm volatile("barrier.cluster.arrive.aligned;" ::: "memory");
    asm volatile("barrier.cluster.wait.aligned;" ::: "memory");
    if (warp == 0) {
        asm volatile("tcgen05.relinquish_alloc_permit.cta_group::1.sync.aligned;");
        asm volatile("tcgen05.dealloc.cta_group::1.sync.aligned.b32 %0, %1;"
                     ::"r"(tmem), "r"(512));
    }

#else  // ----------------- fallback: wmma, persistent over tiles -----------------
    using namespace nvcuda;
    constexpr int BK = 32;
    constexpr int LDAf = BK + 8;   // 40

    __half (*As)[128][LDAf] = reinterpret_cast<__half (*)[128][LDAf]>(tiles);
    __half (*Bk)[128][LDAf] = reinterpret_cast<__half (*)[128][LDAf]>(tiles + 2 * 128 * LDAf * 2);
    float (*stg)[256]       = reinterpret_cast<float (*)[256]>(tiles + 4 * 128 * LDAf * 2);

    const int wm = (warp >> 2) & 1;
    const int wn = warp & 3;

    for (int t = cid; t < numSuper; t += C) {
        const size_t tileM = (size_t)(t / superN) * 512 + (size_t)rank * 256;
        const int tileN = (t % superN) * 256;
        for (int mi = 0; mi < 2; mi++) {
            for (int ni = 0; ni < 2; ni++) {
                const size_t tM = tileM + mi * 128;
                const int tN = tileN + ni * 128;

                wmma::fragment<wmma::accumulator, 16, 16, 16, float> acc[4][2];
#pragma unroll
                for (int i = 0; i < 4; i++)
#pragma unroll
                    for (int jj = 0; jj < 2; jj++) wmma::fill_fragment(acc[i][jj], 0.0f);

                auto loadTiles2 = [&](int buf, int k0) {
                    for (int c = tid; c < 512; c += NTHREADS) {
                        int row = c >> 2, seg = c & 3;
                        cp_async16(smem_u32(&As[buf][row][seg * 8]),
                                   A + (tM + row) * K_DIM + k0 + seg * 8);
                    }
                    for (int c = tid; c < 512; c += NTHREADS) {
                        int row = c >> 2, seg = c & 3;
                        cp_async16(smem_u32(&Bk[buf][row][seg * 8]),
                                   Bw + (size_t)(tN + row) * K_DIM + k0 + seg * 8);
                    }
                    asm volatile("cp.async.commit_group;\n");
                };

                loadTiles2(0, 0);
                constexpr int KT2 = K_DIM / BK;  // 32
                for (int kt = 0; kt < KT2; ++kt) {
                    if (kt + 1 < KT2)
                        loadTiles2((kt + 1) & 1, (kt + 1) * BK);
                    else
                        asm volatile("cp.async.commit_group;\n");
                    asm volatile("cp.async.wait_group 1;\n");
                    __syncthreads();

                    const int buf = kt & 1;
                    if (warp < 8) {
#pragma unroll
                        for (int kk = 0; kk < BK; kk += 16) {
                            wmma::fragment<wmma::matrix_a, 16, 16, 16, __half, wmma::row_major> af[4];
                            wmma::fragment<wmma::matrix_b, 16, 16, 16, __half, wmma::col_major> bfr[2];
#pragma unroll
                            for (int i = 0; i < 4; i++)
                                wmma::load_matrix_sync(af[i], &As[buf][wm * 64 + i * 16][kk], LDAf);
#pragma unroll
                            for (int jj = 0; jj < 2; jj++)
                                wmma::load_matrix_sync(bfr[jj], &Bk[buf][wn * 32 + jj * 16][kk], LDAf);
#pragma unroll
                            for (int i = 0; i < 4; i++)
#pragma unroll
                                for (int jj = 0; jj < 2; jj++)
                                    wmma::mma_sync(acc[i][jj], af[i], bfr[jj], acc[i][jj]);
                        }
                    }
                    __syncthreads();
                }

                if (warp < 8) {
#pragma unroll
                    for (int i = 0; i < 4; i++) {
#pragma unroll
                        for (int jj = 0; jj < 2; jj++) {
                            wmma::store_matrix_sync(stg[warp], acc[i][jj], 16, wmma::mem_row_major);
                            __syncwarp();
#pragma unroll
                            for (int p = 0; p < 8; p++) {
                                int e = lane + p * 32;
                                int r2 = e >> 4, cc = e & 15;
                                size_t grow2 = tM + wm * 64 + i * 16 + r2;
                                int gcol = tN + wn * 32 + jj * 16 + cc;
                                float v = stg[warp][e];
                                if (BIAS) v += bias[gcol];
                                if (OUT_HALF)
                                    Ch[grow2 * N_DIM + gcol] = __float2half(v);
                                else
                                    Cf[grow2 * N_DIM + gcol] = v;
                            }
                            __syncwarp();
                        }
                    }
                }
                __syncthreads();
            }
        }
    }
#endif
}

// ---------------------------------------------------------------------------
// Pipelined tensor-core attention. One warp per row; 2-deep cp.async double
// buffering hides the 6KB row fetch behind the previous row's compute.
// ---------------------------------------------------------------------------
#define AT_WARPS 8
#define AT_WB 13824
#define AT_SMEM (AT_WARPS * AT_WB)

__global__ __launch_bounds__(AT_WARPS * 32) void attn_kernel(int nwtot) {
    using namespace nvcuda;
    extern __shared__ __align__(16) char ats[];

    const int w = threadIdx.x >> 5;
    const int L = threadIdx.x & 31;
    char* wb = ats + w * AT_WB;
    __half* bufs[2] = {reinterpret_cast<__half*>(wb),
                       reinterpret_cast<__half*>(wb + 6144)};
    __half* wgt = reinterpret_cast<__half*>(wb + 12288);
    float*  ssc = reinterpret_cast<float*>(wb + 12800);

    const int gw = blockIdx.x * AT_WARPS + w;

    auto prefetch = [&](int bi, size_t row) {
        const char* src = reinterpret_cast<const char*>(g_qkv + row * NQKV);
        uint32_t d = smem_u32(bufs[bi]);
#pragma unroll
        for (int i = 0; i < 12; i++)
            cp_async16(d + (uint32_t)(L + i * 32) * 16, src + (size_t)(L + i * 32) * 16);
    };

    size_t row = (size_t)gw;
    if (row < B_SZ) prefetch(0, row);
    asm volatile("cp.async.commit_group;\n");

    int cur = 0;
    for (; row < B_SZ; row += (size_t)nwtot) {
        const size_t nrow = row + (size_t)nwtot;
        if (nrow < B_SZ) prefetch(cur ^ 1, nrow);
        asm volatile("cp.async.commit_group;\n");
        asm volatile("cp.async.wait_group 1;\n");
        __syncwarp();

        __half* sqkv = bufs[cur];
        float* so = reinterpret_cast<float*>(sqkv);   // overlays q,k (dead after frags)

        // QK^T: scores[h][g]
        {
            wmma::fragment<wmma::accumulator, 16, 16, 16, float> sacc;
            wmma::fill_fragment(sacc, 0.0f);
#pragma unroll
            for (int kc = 0; kc < 4; kc++) {
                wmma::fragment<wmma::matrix_a, 16, 16, 16, __half, wmma::row_major> qa;
                wmma::fragment<wmma::matrix_b, 16, 16, 16, __half, wmma::col_major> kb;
                wmma::load_matrix_sync(qa, sqkv + kc * 16, 64);
                wmma::load_matrix_sync(kb, sqkv + 1024 + kc * 16, 64);
                wmma::mma_sync(sacc, qa, kb, sacc);
            }
            wmma::store_matrix_sync(ssc, sacc, 16, wmma::mem_row_major);
        }
        __syncwarp();

        // softmax rows (lanes 0-15), fp16 weights
        if (L < 16) {
            float r[16];
            float m = -1e30f;
#pragma unroll
            for (int g = 0; g < 16; g++) {
                r[g] = ssc[L * 16 + g] * 0.125f;
                m = fmaxf(m, r[g]);
            }
            float sum = 0.0f;
#pragma unroll
            for (int g = 0; g < 16; g++) {
                r[g] = __expf(r[g] - m);
                sum += r[g];
            }
            float inv = 1.0f / sum;
#pragma unroll
            for (int g = 0; g < 16; g++)
                wgt[L * 16 + g] = __float2half(r[g] * inv);
        }
        __syncwarp();

        // AV: o[h][d] = sum_g w[h][g] * v[g][d]
        {
            wmma::fragment<wmma::matrix_a, 16, 16, 16, __half, wmma::row_major> wa;
            wmma::load_matrix_sync(wa, wgt, 16);
            wmma::fragment<wmma::matrix_b, 16, 16, 16, __half, wmma::row_major> vb[4];
#pragma unroll
            for (int dc = 0; dc < 4; dc++)
                wmma::load_matrix_sync(vb[dc], sqkv + 2048 + dc * 16, 64);
            __syncwarp();   // v frags in regs before o overlays q,k
            wmma::fragment<wmma::accumulator, 16, 16, 16, float> oacc;
#pragma unroll
            for (int dc = 0; dc < 4; dc++) {
                wmma::fill_fragment(oacc, 0.0f);
                wmma::mma_sync(oacc, wa, vb[dc], oacc);
                wmma::store_matrix_sync(so + dc * 16, oacc, 64, wmma::mem_row_major);
            }
        }
        __syncwarp();

        // transposed write: c[d*16+h]; lane L -> 32 contiguous halves (4x16B)
        __half hbuf[32];
#pragma unroll
        for (int i = 0; i < 16; i++) hbuf[i] = __float2half(so[i * 64 + 2 * L]);
#pragma unroll
        for (int i = 0; i < 16; i++) hbuf[16 + i] = __float2half(so[i * 64 + 2 * L + 1]);
        int4* co = reinterpret_cast<int4*>(g_c + row * F_DIM + 32 * L);
#pragma unroll
        for (int i = 0; i < 4; i++) __stcs(co + i, reinterpret_cast<int4*>(hbuf)[i]);
        __syncwarp();   // so reads done before next iteration's prefetch reuse

        cur ^= 1;
    }
}

// ---------------------------------------------------------------------------
// Host: tensor-map encode via driver entry point (no -lcuda link dependency)
// ---------------------------------------------------------------------------
typedef CUresult (*EncodeTiledFn)(
    CUtensorMap*, CUtensorMapDataType, cuuint32_t, void*,
    const cuuint64_t*, const cuuint64_t*, const cuuint32_t*, const cuuint32_t*,
    CUtensorMapInterleave, CUtensorMapSwizzle, CUtensorMapL2promotion,
    CUtensorMapFloatOOBfill);

// box 32(K) x 128(rows), SW64 (rows are 64B)
static void encode_tm_2d(EncodeTiledFn fn, CUtensorMap* tm, void* base,
                         unsigned long long rows) {
    cuuint64_t dims[2]    = {(cuuint64_t)K_DIM, (cuuint64_t)rows};
    cuuint64_t strides[1] = {(cuuint64_t)K_DIM * 2};
    cuuint32_t box[2]     = {32, 128};
    cuuint32_t es[2]      = {1, 1};
    fn(tm, CU_TENSOR_MAP_DATA_TYPE_FLOAT16, 2, base, dims, strides, box, es,
       CU_TENSOR_MAP_INTERLEAVE_NONE, CU_TENSOR_MAP_SWIZZLE_64B,
       CU_TENSOR_MAP_L2_PROMOTION_L2_128B, CU_TENSOR_MAP_FLOAT_OOB_FILL_NONE);
}

extern "C" void kernel_launch(void* const* d_in, const int* in_sizes, int n_in,
                              void* d_out, int out_size) {
    const float* x  = (const float*)d_in[0];
    const float* Wq = (const float*)d_in[1];
    const float* Wk = (const float*)d_in[2];
    const float* Wv = (const float*)d_in[3];
    const float* Wf = (const float*)d_in[4];
    const float* bf = (const float*)d_in[5];
    float* out = (float*)d_out;

    void *p_xh = nullptr, *p_wqkv = nullptr, *p_wf = nullptr, *p_qkv = nullptr,
         *p_c = nullptr;
    cudaGetSymbolAddress(&p_xh, g_xh);
    cudaGetSymbolAddress(&p_wqkv, g_wqkv);
    cudaGetSymbolAddress(&p_wf, g_wf);
    cudaGetSymbolAddress(&p_qkv, g_qkv);
    cudaGetSymbolAddress(&p_c, g_c);

    EncodeTiledFn enc = nullptr;
    cudaDriverEntryPointQueryResult qr;
    cudaGetDriverEntryPoint("cuTensorMapEncodeTiled", (void**)&enc,
                            cudaEnableDefault, &qr);

    CUtensorMap tmA1{}, tmB1{}, tmA2{}, tmB2{};
    encode_tm_2d(enc, &tmA1, p_xh, B_SZ);     // GEMM1 A: x fp16 [65536,1024]
    encode_tm_2d(enc, &tmB1, p_wqkv, NQKV);   // GEMM1 B: Wqkv^T [3072,1024]
    encode_tm_2d(enc, &tmA2, p_c, B_SZ);      // GEMM2 A: concat [65536,1024]
    encode_tm_2d(enc, &tmB2, p_wf, OUT_N);    // GEMM2 B: Wf^T [1024,1024]

    int nsm = 148;
    cudaDeviceGetAttribute(&nsm, cudaDevAttrMultiProcessorCount, 0);
    int grid = nsm & ~1;   // even: cluster size 2

    cudaFuncSetAttribute(tc_gemm<NQKV, true, false>,
                         cudaFuncAttributeMaxDynamicSharedMemorySize, SMEM_DYN);
    cudaFuncSetAttribute(tc_gemm<OUT_N, false, true>,
                         cudaFuncAttributeMaxDynamicSharedMemorySize, SMEM_DYN);
    cudaFuncSetAttribute(attn_kernel,
                         cudaFuncAttributeMaxDynamicSharedMemorySize, AT_SMEM);

    convert_x_kernel<<<16384, 256>>>(reinterpret_cast<const float4*>(x));
    convert_wqkv_kernel<<<dim3(32, 2, 48), dim3(32, 8)>>>(Wq, Wk, Wv);
    convert_wf_kernel<<<dim3(32, 32), dim3(32, 8)>>>(Wf);

    // QKV = x @ Wqkv^T   (1536 supertiles of 512x256)
    tc_gemm<NQKV, true, false><<<grid, NTHREADS, SMEM_DYN>>>(
        tmA1, tmB1, (const __half*)p_xh, (const __half*)p_wqkv,
        (__half*)p_qkv, nullptr, nullptr,
        (B_SZ / 512) * (NQKV / 256), NQKV / 256);

    // attention over heads -> transposed concat (pipelined tensor-core path)
    int ablocks = 2 * nsm;
    attn_kernel<<<ablocks, AT_WARPS * 32, AT_SMEM>>>(ablocks * AT_WARPS);

    // out = concat @ Wf^T + bf   (512 supertiles)
    tc_gemm<OUT_N, false, true><<<grid, NTHREADS, SMEM_DYN>>>(
        tmA2, tmB2, (const __half*)p_c, (const __half*)p_wf,
        nullptr, out, bf,
        (B_SZ / 512) * (OUT_N / 256), OUT_N / 256);
}

// round 15
// speedup vs baseline: 1.0014x; 1.0014x over previous
#include <cuda_runtime.h>
#include <cuda.h>
#include <cuda_fp16.h>
#include <mma.h>
#include <cstdint>
#include <cstddef>

// Problem dims
#define B_SZ   65536
#define F_DIM  1024
#define H_N    16
#define D_H    64
#define NQKV   3072
#define OUT_N  1024
#define K_DIM  1024

#if defined(__CUDA_ARCH_FEAT_SM103_ALL) || defined(__CUDA_ARCH_FEAT_SM100_ALL)
#define HAS_TCGEN05 1
#else
#define HAS_TCGEN05 0
#endif

// ---------------------------------------------------------------------------
// Scratch (allocation-free: __device__ globals). 1KB-aligned for TMA.
// ---------------------------------------------------------------------------
__device__ __align__(1024) __half g_xh  [(size_t)B_SZ * F_DIM];
__device__ __align__(1024) __half g_wqkv[(size_t)NQKV * K_DIM];
__device__ __align__(1024) __half g_wf  [(size_t)OUT_N * K_DIM];
__device__ __align__(1024) __half g_qkv [(size_t)B_SZ * NQKV];
__device__ __align__(1024) __half g_c   [(size_t)B_SZ * F_DIM];

// ---------------------------------------------------------------------------
// PTX helpers
// ---------------------------------------------------------------------------
__device__ __forceinline__ uint32_t smem_u32(const void* p) {
    return (uint32_t)__cvta_generic_to_shared(p);
}
__device__ __forceinline__ uint32_t ctarank() {
    uint32_t r;
    asm("mov.u32 %0, %%cluster_ctarank;" : "=r"(r));
    return r;
}
__device__ __forceinline__ void cp_async16(uint32_t s, const void* g) {
    asm volatile("cp.async.cg.shared.global [%0], [%1], 16;\n" ::"r"(s), "l"(g));
}
__device__ __forceinline__ void mbar_init(uint64_t* b, uint32_t cnt) {
    asm volatile("mbarrier.init.shared.b64 [%0], %1;" ::"r"(smem_u32(b)), "r"(cnt) : "memory");
}
__device__ __forceinline__ void mbar_arrive(uint64_t* b) {
    asm volatile("mbarrier.arrive.shared.b64 _, [%0];" ::"r"(smem_u32(b)) : "memory");
}
__device__ __forceinline__ void mbar_wait(uint64_t* b, uint32_t parity) {
    uint32_t addr = smem_u32(b);
    asm volatile(
        "{\n\t"
        ".reg .pred P1;\n\t"
        "WAIT_LOOP_%=:\n\t"
        "mbarrier.try_wait.parity.acquire.cta.shared::cta.b64 P1, [%0], %1, 0x989680;\n\t"
        "@P1 bra.uni WAIT_DONE_%=;\n\t"
        "bra.uni WAIT_LOOP_%=;\n\t"
        "WAIT_DONE_%=:\n\t"
        "}"
        ::"r"(addr), "r"(parity) : "memory");
}
#if HAS_TCGEN05
__device__ __forceinline__ void tc_commit(uint64_t* b) {
    asm volatile(
        "tcgen05.commit.cta_group::1.mbarrier::arrive::one.shared::cluster.b64 [%0];"
        ::"r"(smem_u32(b)) : "memory");
}
__device__ __forceinline__ void tc_commit_mc(uint64_t* b, uint16_t mask) {
    asm volatile(
        "tcgen05.commit.cta_group::1.mbarrier::arrive::one.shared::cluster.multicast::cluster.b64 [%0], %1;"
        ::"r"(smem_u32(b)), "h"(mask) : "memory");
}
__device__ __forceinline__ void mbar_expect_tx(uint64_t* b, uint32_t bytes) {
    asm volatile("mbarrier.arrive.expect_tx.shared.b64 _, [%0], %1;"
                 ::"r"(smem_u32(b)), "r"(bytes) : "memory");
}
__device__ __forceinline__ void tma_2d(uint32_t smem, const CUtensorMap* tm,
                                       int c0, int c1, uint32_t mbar) {
    asm volatile(
        "cp.async.bulk.tensor.2d.shared::cta.global.tile.mbarrier::complete_tx::bytes "
        "[%0], [%1, {%2, %3}], [%4];"
        ::"r"(smem), "l"(tm), "r"(c0), "r"(c1), "r"(mbar) : "memory");
}
__device__ __forceinline__ void tma_2d_mc(uint32_t smem, const CUtensorMap* tm,
                                          int c0, int c1, uint32_t mbar,
                                          uint16_t mask) {
    asm volatile(
        "cp.async.bulk.tensor.2d.shared::cluster.global.tile.mbarrier::complete_tx::bytes.multicast::cluster "
        "[%0], [%1, {%2, %3}], [%4], %5;"
        ::"r"(smem), "l"(tm), "r"(c0), "r"(c1), "r"(mbar), "h"(mask) : "memory");
}
// SW64 K-major smem descriptor: layout=4, version=1, SBO=32, LBO=1
// (SW64 atom = 8 rows x 64B; BK=32 f16 rows are 64B wide.)
__device__ __forceinline__ uint64_t make_desc64(uint32_t addr) {
    constexpr uint64_t BASE =
        (uint64_t(4) << 61) | (uint64_t(1) << 46) | (uint64_t(32) << 32) | (uint64_t(1) << 16);
    return BASE | ((uint64_t)(addr >> 4) & 0x3FFF);
}
__device__ __forceinline__ void mma_f16_ss(uint32_t d, uint64_t a, uint64_t b,
                                           uint32_t idesc, uint32_t en) {
    asm volatile(
        "{\n\t"
        ".reg .pred p;\n\t"
        "setp.ne.u32 p, %5, 0;\n\t"
        "tcgen05.mma.cta_group::1.kind::f16 [%0], %1, %2, %3, {%4, %4, %4, %4}, p;\n\t"
        "}"
        ::"r"(d), "l"(a), "l"(b), "r"(idesc), "r"(0u), "r"(en) : "memory");
}
__device__ __forceinline__ void tmem_ld_x32(uint32_t* r, uint32_t tmem_addr) {
    asm volatile(
        "tcgen05.ld.sync.aligned.32x32b.x32.b32 "
        "{%0, %1, %2, %3, %4, %5, %6, %7, "
        " %8, %9, %10, %11, %12, %13, %14, %15, "
        " %16, %17, %18, %19, %20, %21, %22, %23, "
        " %24, %25, %26, %27, %28, %29, %30, %31}, [%32];"
        : "=r"(r[0]), "=r"(r[1]), "=r"(r[2]), "=r"(r[3]),
          "=r"(r[4]), "=r"(r[5]), "=r"(r[6]), "=r"(r[7]),
          "=r"(r[8]), "=r"(r[9]), "=r"(r[10]), "=r"(r[11]),
          "=r"(r[12]), "=r"(r[13]), "=r"(r[14]), "=r"(r[15]),
          "=r"(r[16]), "=r"(r[17]), "=r"(r[18]), "=r"(r[19]),
          "=r"(r[20]), "=r"(r[21]), "=r"(r[22]), "=r"(r[23]),
          "=r"(r[24]), "=r"(r[25]), "=r"(r[26]), "=r"(r[27]),
          "=r"(r[28]), "=r"(r[29]), "=r"(r[30]), "=r"(r[31])
        : "r"(tmem_addr));
}
#endif  // HAS_TCGEN05

// ---------------------------------------------------------------------------
// Converters
// ---------------------------------------------------------------------------
__global__ void convert_x_kernel(const float4* __restrict__ x) {
    const size_t n4 = (size_t)B_SZ * F_DIM / 4;
    int2* out = reinterpret_cast<int2*>(g_xh);
    for (size_t i = (size_t)blockIdx.x * blockDim.x + threadIdx.x; i < n4;
         i += (size_t)gridDim.x * blockDim.x) {
        float4 v = __ldcs(x + i);
        __half2 h0 = __floats2half2_rn(v.x, v.y);
        __half2 h1 = __floats2half2_rn(v.z, v.w);
        int2 pk;
        pk.x = *reinterpret_cast<int*>(&h0);
        pk.y = *reinterpret_cast<int*>(&h1);
        __stcs(out + i, pk);
    }
}

// Coalesced tiled transpose: W[H][F][D] -> g_wqkv[n][f], n = which*1024+h*64+d.
__global__ void convert_wqkv_kernel(const float* __restrict__ Wq,
                                    const float* __restrict__ Wk,
                                    const float* __restrict__ Wv) {
    __shared__ float tile[32][33];
    const int which = blockIdx.z >> 4;
    const int h = blockIdx.z & 15;
    const int f0 = blockIdx.x * 32;
    const int d0 = blockIdx.y * 32;
    const float* W = (which == 0) ? Wq : ((which == 1) ? Wk : Wv);
    const float* src = W + ((size_t)h * F_DIM) * D_H;   // [F][D]

    const int tx = threadIdx.x;
    const int ty = threadIdx.y;
#pragma unroll
    for (int r = 0; r < 4; r++) {
        int f = f0 + ty + r * 8;
        int d = d0 + tx;
        if (d < D_H) tile[ty + r * 8][tx] = src[(size_t)f * D_H + d];
    }
    __syncthreads();
#pragma unroll
    for (int r = 0; r < 4; r++) {
        int d = d0 + ty + r * 8;
        int f = f0 + tx;
        if (d < D_H) {
            int n = which * 1024 + h * 64 + d;
            g_wqkv[(size_t)n * K_DIM + f] = __float2half(tile[tx][ty + r * 8]);
        }
    }
}

// Coalesced tiled transpose: Wf[K][N] -> g_wf[n][k].
__global__ void convert_wf_kernel(const float* __restrict__ Wf) {
    __shared__ float tile[32][33];
    const int k0 = blockIdx.x * 32;
    const int n0 = blockIdx.y * 32;
    const int tx = threadIdx.x;
    const int ty = threadIdx.y;
#pragma unroll
    for (int r = 0; r < 4; r++) {
        int k = k0 + ty + r * 8;
        tile[ty + r * 8][tx] = Wf[(size_t)k * OUT_N + n0 + tx];
    }
    __syncthreads();
#pragma unroll
    for (int r = 0; r < 4; r++) {
        int n = n0 + ty + r * 8;
        g_wf[(size_t)n * K_DIM + k0 + tx] = __float2half(tile[tx][ty + r * 8]);
    }
}

// ---------------------------------------------------------------------------
// Persistent tcgen05 GEMM, cluster-2 with B multicast, N=256 dispatches.
// DEEP PIPELINE: BK=32 (SW64 tiles), 6 stages of 32KB.
// Stage layout: A0 [0,8K), A1 [8K,16K), B [16K,32K) (own mc half at
// +rank*8K; partner's multicast fills the other half).
// ---------------------------------------------------------------------------
#define STAGES 6
#define STAGE_BYTES 32768
#define SMEM_DYN (STAGES * STAGE_BYTES + 1024)
#define KT 32                      // 1024 / 32
#define NTHREADS 512               // 16 warps

// idesc: dtype=F32(1<<4), atype=btype=F16(0), N=256 -> 32<<17, M=128 -> 8<<24
#define IDESC_F16_N256 ((1u << 4) | (32u << 17) | (8u << 24))

template <int N_DIM, bool OUT_HALF, bool BIAS>
__global__ __launch_bounds__(NTHREADS, 1) __cluster_dims__(2, 1, 1)
void tc_gemm(const __grid_constant__ CUtensorMap tmA,
             const __grid_constant__ CUtensorMap tmB,
             const __half* __restrict__ A, const __half* __restrict__ Bw,
             __half* __restrict__ Ch, float* __restrict__ Cf,
             const float* __restrict__ bias, int numSuper, int superN) {
    extern __shared__ __align__(16) char dsm[];
    char* tiles = (char*)(((uintptr_t)dsm + 1023) & ~(uintptr_t)1023);

    const int tid = threadIdx.x;
    const int warp = tid >> 5;
    const int lane = tid & 31;
    const int C = gridDim.x >> 1;        // clusters
    const int cid = blockIdx.x >> 1;
    const int rank = (int)ctarank();     // 0 or 1 within cluster

#if HAS_TCGEN05
    __shared__ __align__(8) uint64_t bar_full[STAGES];
    __shared__ __align__(8) uint64_t bar_empty[STAGES];
    __shared__ __align__(8) uint64_t bar_done;
    __shared__ __align__(8) uint64_t bar_free;
    __shared__ uint32_t s_tmem;

    if (warp == 0) {
        asm volatile(
            "tcgen05.alloc.cta_group::1.sync.aligned.shared::cta.b32 [%0], %1;"
            ::"r"(smem_u32(&s_tmem)), "r"(512) : "memory");
    }
    if (tid == 0) {
        for (int s = 0; s < STAGES; s++) {
            mbar_init(&bar_full[s], 1);
            mbar_init(&bar_empty[s], 2);   // commits from BOTH cluster CTAs
        }
        mbar_init(&bar_done, 1);
        mbar_init(&bar_free, 8);
        asm volatile("fence.proxy.async.shared::cta;" ::: "memory");
    }
    __syncthreads();
    // All mbarriers must be cluster-visible before any multicast TMA / commit.
    asm volatile("barrier.cluster.arrive.aligned;" ::: "memory");
    asm volatile("barrier.cluster.wait.aligned;" ::: "memory");
    const uint32_t tmem = s_tmem;

    if (tid == 0) {
        // ------------------ producer: single thread, TMA ------------------
        asm volatile("prefetch.tensormap [%0];" ::"l"(&tmA));
        asm volatile("prefetch.tensormap [%0];" ::"l"(&tmB));
        int s = 0, ph = 1;  // fresh-barrier: parity-1 wait passes immediately
        for (int t = cid; t < numSuper; t += C) {
            const int tileM = (t / superN) * 512 + rank * 256;
            const int tileN = (t % superN) * 256;
            for (int kt = 0; kt < KT; kt++) {
                mbar_wait(&bar_empty[s], (uint32_t)ph);
                const uint32_t st = smem_u32(tiles + s * STAGE_BYTES);
                const uint32_t mb = smem_u32(&bar_full[s]);
                mbar_expect_tx(&bar_full[s], STAGE_BYTES);
                // own A halves (unicast, own barrier)
                tma_2d(st,        &tmA, kt * 32, tileM,       mb);
                tma_2d(st + 8192, &tmA, kt * 32, tileM + 128, mb);
                // one B box, multicast to both cluster CTAs
                tma_2d_mc(st + 16384 + rank * 8192, &tmB, kt * 32,
                          tileN + rank * 128, mb, (uint16_t)0x3);
                if (++s == STAGES) { s = 0; ph ^= 1; }
            }
        }
    } else if (warp == 4 && lane == 0) {
        // ------------------ MMA issue: single thread ------------------
        int s = 0, ph = 0, ti = 0;
        for (int t = cid; t < numSuper; t += C) {
            if (ti >= 1) {
                mbar_wait(&bar_free, (uint32_t)((ti - 1) & 1));
                asm volatile("tcgen05.fence::after_thread_sync;" ::: "memory");
            }
            for (int kt = 0; kt < KT; kt++) {
                mbar_wait(&bar_full[s], (uint32_t)ph);
                char* st = tiles + s * STAGE_BYTES;
                uint64_t a0 = make_desc64(smem_u32(st));
                uint64_t a1 = make_desc64(smem_u32(st + 8192));
                uint64_t b0 = make_desc64(smem_u32(st + 16384));  // 256 rows
#pragma unroll
                for (int ks = 0; ks < 2; ks++) {
                    uint32_t en = (kt == 0 && ks == 0) ? 0u : 1u;
                    uint64_t ko = (uint64_t)(ks * 2);  // 32 bytes per K-step
                    mma_f16_ss(tmem + 0,   a0 + ko, b0 + ko, IDESC_F16_N256, en);
                    mma_f16_ss(tmem + 256, a1 + ko, b0 + ko, IDESC_F16_N256, en);
                }
                // release the stage in BOTH cluster CTAs (B box is shared)
                tc_commit_mc(&bar_empty[s], (uint16_t)0x3);
                if (++s == STAGES) { s = 0; ph ^= 1; }
            }
            tc_commit(&bar_done);
            ti++;
        }
    } else if (warp >= 8) {
        // ------------- epilogue: warps 8-15, subpartition = warp&3 -------------
        const int mhalf = (warp >> 2) - 2;          // warps 8-11 -> 0, 12-15 -> 1
        const int subp = warp & 3;                  // hardware TMEM lane group
        int ti = 0;
        for (int t = cid; t < numSuper; t += C) {
            const size_t tileM = (size_t)(t / superN) * 512 + rank * 256;
            const int tileN = (t % superN) * 256;
            mbar_wait(&bar_done, (uint32_t)(ti & 1));
            asm volatile("tcgen05.fence::after_thread_sync;" ::: "memory");
            const size_t grow = tileM + mhalf * 128 + subp * 32 + lane;
#pragma unroll
            for (int nb = 0; nb < 8; nb += 2) {
                uint32_t r0[32], r1[32];
                tmem_ld_x32(r0, tmem + mhalf * 256 + nb * 32);
                tmem_ld_x32(r1, tmem + mhalf * 256 + nb * 32 + 32);
                asm volatile("tcgen05.wait::ld.sync.aligned;" ::: "memory");
#pragma unroll
                for (int half2i = 0; half2i < 2; half2i++) {
                    uint32_t* r = half2i ? r1 : r0;
                    const int gc0 = tileN + (nb + half2i) * 32;
                    if (OUT_HALF) {
                        __half2 h2[16];
#pragma unroll
                        for (int i = 0; i < 16; i++)
                            h2[i] = __floats2half2_rn(__uint_as_float(r[2 * i]),
                                                      __uint_as_float(r[2 * i + 1]));
                        int4* dst = reinterpret_cast<int4*>(Ch + grow * N_DIM + gc0);
#pragma unroll
                        for (int i = 0; i < 4; i++)
                            __stcs(dst + i, reinterpret_cast<int4*>(h2)[i]);
                    } else {
                        float4* dst = reinterpret_cast<float4*>(Cf + grow * N_DIM + gc0);
#pragma unroll
                        for (int i = 0; i < 8; i++) {
                            float4 v;
                            v.x = __uint_as_float(r[4 * i + 0]) + (BIAS ? bias[gc0 + 4 * i + 0] : 0.0f);
                            v.y = __uint_as_float(r[4 * i + 1]) + (BIAS ? bias[gc0 + 4 * i + 1] : 0.0f);
                            v.z = __uint_as_float(r[4 * i + 2]) + (BIAS ? bias[gc0 + 4 * i + 2] : 0.0f);
                            v.w = __uint_as_float(r[4 * i + 3]) + (BIAS ? bias[gc0 + 4 * i + 3] : 0.0f);
                            __stcs(dst + i, v);
                        }
                    }
                }
            }
            asm volatile("tcgen05.fence::before_thread_sync;" ::: "memory");
            if (lane == 0) mbar_arrive(&bar_free);
            ti++;
        }
    }

    __syncthreads();
    // No CTA may exit while another CTA's multicast could still target it.
    asm volatile("barrier.cluster.arrive.aligned;" ::: "memory");
    asm volatile("barrier.cluster.wait.aligned;" ::: "memory");
    if (warp == 0) {
        asm volatile("tcgen05.relinquish_alloc_permit.cta_group::1.sync.aligned;");
        asm volatile("tcgen05.dealloc.cta_group::1.sync.aligned.b32 %0, %1;"
                     ::"r"(tmem), "r"(512));
    }

#else  // ----------------- fallback: wmma, persistent over tiles -----------------
    using namespace nvcuda;
    constexpr int BK = 32;
    constexpr int LDAf = BK + 8;   // 40

    __half (*As)[128][LDAf] = reinterpret_cast<__half (*)[128][LDAf]>(tiles);
    __half (*Bk)[128][LDAf] = reinterpret_cast<__half (*)[128][LDAf]>(tiles + 2 * 128 * LDAf * 2);
    float (*stg)[256]       = reinterpret_cast<float (*)[256]>(tiles + 4 * 128 * LDAf * 2);

    const int wm = (warp >> 2) & 1;
    const int wn = warp & 3;

    for (int t = cid; t < numSuper; t += C) {
        const size_t tileM = (size_t)(t / superN) * 512 + (size_t)rank * 256;
        const int tileN = (t % superN) * 256;
        for (int mi = 0; mi < 2; mi++) {
            for (int ni = 0; ni < 2; ni++) {
                const size_t tM = tileM + mi * 128;
                const int tN = tileN + ni * 128;

                wmma::fragment<wmma::accumulator, 16, 16, 16, float> acc[4][2];
#pragma unroll
                for (int i = 0; i < 4; i++)
#pragma unroll
                    for (int jj = 0; jj < 2; jj++) wmma::fill_fragment(acc[i][jj], 0.0f);

                auto loadTiles2 = [&](int buf, int k0) {
                    for (int c = tid; c < 512; c += NTHREADS) {
                        int row = c >> 2, seg = c & 3;
                        cp_async16(smem_u32(&As[buf][row][seg * 8]),
                                   A + (tM + row) * K_DIM + k0 + seg * 8);
                    }
                    for (int c = tid; c < 512; c += NTHREADS) {
                        int row = c >> 2, seg = c & 3;
                        cp_async16(smem_u32(&Bk[buf][row][seg * 8]),
                                   Bw + (size_t)(tN + row) * K_DIM + k0 + seg * 8);
                    }
                    asm volatile("cp.async.commit_group;\n");
                };

                loadTiles2(0, 0);
                constexpr int KT2 = K_DIM / BK;  // 32
                for (int kt = 0; kt < KT2; ++kt) {
                    if (kt + 1 < KT2)
                        loadTiles2((kt + 1) & 1, (kt + 1) * BK);
                    else
                        asm volatile("cp.async.commit_group;\n");
                    asm volatile("cp.async.wait_group 1;\n");
                    __syncthreads();

                    const int buf = kt & 1;
                    if (warp < 8) {
#pragma unroll
                        for (int kk = 0; kk < BK; kk += 16) {
                            wmma::fragment<wmma::matrix_a, 16, 16, 16, __half, wmma::row_major> af[4];
                            wmma::fragment<wmma::matrix_b, 16, 16, 16, __half, wmma::col_major> bfr[2];
#pragma unroll
                            for (int i = 0; i < 4; i++)
                                wmma::load_matrix_sync(af[i], &As[buf][wm * 64 + i * 16][kk], LDAf);
#pragma unroll
                            for (int jj = 0; jj < 2; jj++)
                                wmma::load_matrix_sync(bfr[jj], &Bk[buf][wn * 32 + jj * 16][kk], LDAf);
#pragma unroll
                            for (int i = 0; i < 4; i++)
#pragma unroll
                                for (int jj = 0; jj < 2; jj++)
                                    wmma::mma_sync(acc[i][jj], af[i], bfr[jj], acc[i][jj]);
                        }
                    }
                    __syncthreads();
                }

                if (warp < 8) {
#pragma unroll
                    for (int i = 0; i < 4; i++) {
#pragma unroll
                        for (int jj = 0; jj < 2; jj++) {
                            wmma::store_matrix_sync(stg[warp], acc[i][jj], 16, wmma::mem_row_major);
                            __syncwarp();
#pragma unroll
                            for (int p = 0; p < 8; p++) {
                                int e = lane + p * 32;
                                int r2 = e >> 4, cc = e & 15;
                                size_t grow2 = tM + wm * 64 + i * 16 + r2;
                                int gcol = tN + wn * 32 + jj * 16 + cc;
                                float v = stg[warp][e];
                                if (BIAS) v += bias[gcol];
                                if (OUT_HALF)
                                    Ch[grow2 * N_DIM + gcol] = __float2half(v);
                                else
                                    Cf[grow2 * N_DIM + gcol] = v;
                            }
                            __syncwarp();
                        }
                    }
                }
                __syncthreads();
            }
        }
    }
#endif
}

// ---------------------------------------------------------------------------
// Pipelined tensor-core attention. One warp per row; 2-deep cp.async double
// buffering hides the 6KB row fetch behind the previous row's compute.
// ---------------------------------------------------------------------------
#define AT_WARPS 8
#define AT_WB 13824
#define AT_SMEM (AT_WARPS * AT_WB)

__global__ __launch_bounds__(AT_WARPS * 32) void attn_kernel(int nwtot) {
    using namespace nvcuda;
    extern __shared__ __align__(16) char ats[];

    const int w = threadIdx.x >> 5;
    const int L = threadIdx.x & 31;
    char* wb = ats + w * AT_WB;
    __half* bufs[2] = {reinterpret_cast<__half*>(wb),
                       reinterpret_cast<__half*>(wb + 6144)};
    __half* wgt = reinterpret_cast<__half*>(wb + 12288);
    float*  ssc = reinterpret_cast<float*>(wb + 12800);

    const int gw = blockIdx.x * AT_WARPS + w;

    auto prefetch = [&](int bi, size_t row) {
        const char* src = reinterpret_cast<const char*>(g_qkv + row * NQKV);
        uint32_t d = smem_u32(bufs[bi]);
#pragma unroll
        for (int i = 0; i < 12; i++)
            cp_async16(d + (uint32_t)(L + i * 32) * 16, src + (size_t)(L + i * 32) * 16);
    };

    size_t row = (size_t)gw;
    if (row < B_SZ) prefetch(0, row);
    asm volatile("cp.async.commit_group;\n");

    int cur = 0;
    for (; row < B_SZ; row += (size_t)nwtot) {
        const size_t nrow = row + (size_t)nwtot;
        if (nrow < B_SZ) prefetch(cur ^ 1, nrow);
        asm volatile("cp.async.commit_group;\n");
        asm volatile("cp.async.wait_group 1;\n");
        __syncwarp();

        __half* sqkv = bufs[cur];
        float* so = reinterpret_cast<float*>(sqkv);   // overlays q,k (dead after frags)

        // QK^T: scores[h][g]
        {
            wmma::fragment<wmma::accumulator, 16, 16, 16, float> sacc;
            wmma::fill_fragment(sacc, 0.0f);
#pragma unroll
            for (int kc = 0; kc < 4; kc++) {
                wmma::fragment<wmma::matrix_a, 16, 16, 16, __half, wmma::row_major> qa;
                wmma::fragment<wmma::matrix_b, 16, 16, 16, __half, wmma::col_major> kb;
                wmma::load_matrix_sync(qa, sqkv + kc * 16, 64);
                wmma::load_matrix_sync(kb, sqkv + 1024 + kc * 16, 64);
                wmma::mma_sync(sacc, qa, kb, sacc);
            }
            wmma::store_matrix_sync(ssc, sacc, 16, wmma::mem_row_major);
        }
        __syncwarp();

        // softmax rows (lanes 0-15), fp16 weights
        if (L < 16) {
            float r[16];
            float m = -1e30f;
#pragma unroll
            for (int g = 0; g < 16; g++) {
                r[g] = ssc[L * 16 + g] * 0.125f;
                m = fmaxf(m, r[g]);
            }
            float sum = 0.0f;
#pragma unroll
            for (int g = 0; g < 16; g++) {
                r[g] = __expf(r[g] - m);
                sum += r[g];
            }
            float inv = 1.0f / sum;
#pragma unroll
            for (int g = 0; g < 16; g++)
                wgt[L * 16 + g] = __float2half(r[g] * inv);
        }
        __syncwarp();

        // AV: o[h][d] = sum_g w[h][g] * v[g][d]
        {
            wmma::fragment<wmma::matrix_a, 16, 16, 16, __half, wmma::row_major> wa;
            wmma::load_matrix_sync(wa, wgt, 16);
            wmma::fragment<wmma::matrix_b, 16, 16, 16, __half, wmma::row_major> vb[4];
#pragma unroll
            for (int dc = 0; dc < 4; dc++)
                wmma::load_matrix_sync(vb[dc], sqkv + 2048 + dc * 16, 64);
            __syncwarp();   // v frags in regs before o overlays q,k
            wmma::fragment<wmma::accumulator, 16, 16, 16, float> oacc;
#pragma unroll
            for (int dc = 0; dc < 4; dc++) {
                wmma::fill_fragment(oacc, 0.0f);
                wmma::mma_sync(oacc, wa, vb[dc], oacc);
                wmma::store_matrix_sync(so + dc * 16, oacc, 64, wmma::mem_row_major);
            }
        }
        __syncwarp();

        // transposed write: c[d*16+h]; lane L -> 32 contiguous halves (4x16B)
        __half hbuf[32];
#pragma unroll
        for (int i = 0; i < 16; i++) hbuf[i] = __float2half(so[i * 64 + 2 * L]);
#pragma unroll
        for (int i = 0; i < 16; i++) hbuf[16 + i] = __float2half(so[i * 64 + 2 * L + 1]);
        int4* co = reinterpret_cast<int4*>(g_c + row * F_DIM + 32 * L);
#pragma unroll
        for (int i = 0; i < 4; i++) __stcs(co + i, reinterpret_cast<int4*>(hbuf)[i]);
        __syncwarp();   // so reads done before next iteration's prefetch reuse

        cur ^= 1;
    }
}

// ---------------------------------------------------------------------------
// Host: tensor-map encode via driver entry point (no -lcuda link dependency)
// ---------------------------------------------------------------------------
typedef CUresult (*EncodeTiledFn)(
    CUtensorMap*, CUtensorMapDataType, cuuint32_t, void*,
    const cuuint64_t*, const cuuint64_t*, const cuuint32_t*, const cuuint32_t*,
    CUtensorMapInterleave, CUtensorMapSwizzle, CUtensorMapL2promotion,
    CUtensorMapFloatOOBfill);

// box 32(K) x 128(rows), SW64 (rows are 64B)
static void encode_tm_2d(EncodeTiledFn fn, CUtensorMap* tm, void* base,
                         unsigned long long rows) {
    cuuint64_t dims[2]    = {(cuuint64_t)K_DIM, (cuuint64_t)rows};
    cuuint64_t strides[1] = {(cuuint64_t)K_DIM * 2};
    cuuint32_t box[2]     = {32, 128};
    cuuint32_t es[2]      = {1, 1};
    fn(tm, CU_TENSOR_MAP_DATA_TYPE_FLOAT16, 2, base, dims, strides, box, es,
       CU_TENSOR_MAP_INTERLEAVE_NONE, CU_TENSOR_MAP_SWIZZLE_64B,
       CU_TENSOR_MAP_L2_PROMOTION_L2_128B, CU_TENSOR_MAP_FLOAT_OOB_FILL_NONE);
}

extern "C" void kernel_launch(void* const* d_in, const int* in_sizes, int n_in,
                              void* d_out, int out_size) {
    const float* x  = (const float*)d_in[0];
    const float* Wq = (const float*)d_in[1];
    const float* Wk = (const float*)d_in[2];
    const float* Wv = (const float*)d_in[3];
    const float* Wf = (const float*)d_in[4];
    const float* bf = (const float*)d_in[5];
    float* out = (float*)d_out;

    void *p_xh = nullptr, *p_wqkv = nullptr, *p_wf = nullptr, *p_qkv = nullptr,
         *p_c = nullptr;
    cudaGetSymbolAddress(&p_xh, g_xh);
    cudaGetSymbolAddress(&p_wqkv, g_wqkv);
    cudaGetSymbolAddress(&p_wf, g_wf);
    cudaGetSymbolAddress(&p_qkv, g_qkv);
    cudaGetSymbolAddress(&p_c, g_c);

    EncodeTiledFn enc = nullptr;
    cudaDriverEntryPointQueryResult qr;
    cudaGetDriverEntryPoint("cuTensorMapEncodeTiled", (void**)&enc,
                            cudaEnableDefault, &qr);

    CUtensorMap tmA1{}, tmB1{}, tmA2{}, tmB2{};
    encode_tm_2d(enc, &tmA1, p_xh, B_SZ);     // GEMM1 A: x fp16 [65536,1024]
    encode_tm_2d(enc, &tmB1, p_wqkv, NQKV);   // GEMM1 B: Wqkv^T [3072,1024]
    encode_tm_2d(enc, &tmA2, p_c, B_SZ);      // GEMM2 A: concat [65536,1024]
    encode_tm_2d(enc, &tmB2, p_wf, OUT_N);    // GEMM2 B: Wf^T [1024,1024]

    int nsm = 148;
    cudaDeviceGetAttribute(&nsm, cudaDevAttrMultiProcessorCount, 0);
    int grid = nsm & ~1;   // even: cluster size 2

    cudaFuncSetAttribute(tc_gemm<NQKV, true, false>,
                         cudaFuncAttributeMaxDynamicSharedMemorySize, SMEM_DYN);
    cudaFuncSetAttribute(tc_gemm<OUT_N, false, true>,
                         cudaFuncAttributeMaxDynamicSharedMemorySize, SMEM_DYN);
    cudaFuncSetAttribute(attn_kernel,
                         cudaFuncAttributeMaxDynamicSharedMemorySize, AT_SMEM);

    convert_x_kernel<<<16384, 256>>>(reinterpret_cast<const float4*>(x));
    convert_wqkv_kernel<<<dim3(32, 2, 48), dim3(32, 8)>>>(Wq, Wk, Wv);
    convert_wf_kernel<<<dim3(32, 32), dim3(32, 8)>>>(Wf);

    // QKV = x @ Wqkv^T   (1536 supertiles of 512x256)
    tc_gemm<NQKV, true, false><<<grid, NTHREADS, SMEM_DYN>>>(
        tmA1, tmB1, (const __half*)p_xh, (const __half*)p_wqkv,
        (__half*)p_qkv, nullptr, nullptr,
        (B_SZ / 512) * (NQKV / 256), NQKV / 256);

    // attention over heads -> transposed concat (pipelined tensor-core path)
    int ablocks = 2 * nsm;
    attn_kernel<<<ablocks, AT_WARPS * 32, AT_SMEM>>>(ablocks * AT_WARPS);

    // out = concat @ Wf^T + bf   (512 supertiles)
    tc_gemm<OUT_N, false, true><<<grid, NTHREADS, SMEM_DYN>>>(
        tmA2, tmB2, (const __half*)p_c, (const __half*)p_wf,
        nullptr, out, bf,
        (B_SZ / 512) * (OUT_N / 256), OUT_N / 256);
}

// round 16
// speedup vs baseline: 1.1638x; 1.1622x over previous
#include <cuda_runtime.h>
#include <cuda.h>
#include <cuda_fp16.h>
#include <mma.h>
#include <cstdint>
#include <cstddef>

// Problem dims
#define B_SZ   65536
#define F_DIM  1024
#define H_N    16
#define D_H    64
#define NQKV   3072
#define OUT_N  1024
#define K_DIM  1024

#if defined(__CUDA_ARCH_FEAT_SM103_ALL) || defined(__CUDA_ARCH_FEAT_SM100_ALL)
#define HAS_TCGEN05 1
#else
#define HAS_TCGEN05 0
#endif

// ---------------------------------------------------------------------------
// Scratch (allocation-free: __device__ globals). 1KB-aligned for TMA.
// ---------------------------------------------------------------------------
__device__ __align__(1024) __half g_xh  [(size_t)B_SZ * F_DIM];
__device__ __align__(1024) __half g_wqkv[(size_t)NQKV * K_DIM];
__device__ __align__(1024) __half g_wf  [(size_t)OUT_N * K_DIM];
__device__ __align__(1024) __half g_qkv [(size_t)B_SZ * NQKV];
__device__ __align__(1024) __half g_c   [(size_t)B_SZ * F_DIM];

// ---------------------------------------------------------------------------
// PTX helpers
// ---------------------------------------------------------------------------
__device__ __forceinline__ uint32_t smem_u32(const void* p) {
    return (uint32_t)__cvta_generic_to_shared(p);
}
__device__ __forceinline__ uint32_t ctarank() {
    uint32_t r;
    asm("mov.u32 %0, %%cluster_ctarank;" : "=r"(r));
    return r;
}
__device__ __forceinline__ void cp_async16(uint32_t s, const void* g) {
    asm volatile("cp.async.cg.shared.global [%0], [%1], 16;\n" ::"r"(s), "l"(g));
}
__device__ __forceinline__ void mbar_init(uint64_t* b, uint32_t cnt) {
    asm volatile("mbarrier.init.shared.b64 [%0], %1;" ::"r"(smem_u32(b)), "r"(cnt) : "memory");
}
__device__ __forceinline__ void mbar_arrive(uint64_t* b) {
    asm volatile("mbarrier.arrive.shared.b64 _, [%0];" ::"r"(smem_u32(b)) : "memory");
}
__device__ __forceinline__ void mbar_wait(uint64_t* b, uint32_t parity) {
    uint32_t addr = smem_u32(b);
    asm volatile(
        "{\n\t"
        ".reg .pred P1;\n\t"
        "WAIT_LOOP_%=:\n\t"
        "mbarrier.try_wait.parity.acquire.cta.shared::cta.b64 P1, [%0], %1, 0x989680;\n\t"
        "@P1 bra.uni WAIT_DONE_%=;\n\t"
        "bra.uni WAIT_LOOP_%=;\n\t"
        "WAIT_DONE_%=:\n\t"
        "}"
        ::"r"(addr), "r"(parity) : "memory");
}
#if HAS_TCGEN05
__device__ __forceinline__ void tc_commit(uint64_t* b) {
    asm volatile(
        "tcgen05.commit.cta_group::1.mbarrier::arrive::one.shared::cluster.b64 [%0];"
        ::"r"(smem_u32(b)) : "memory");
}
__device__ __forceinline__ void tc_commit_mc(uint64_t* b, uint16_t mask) {
    asm volatile(
        "tcgen05.commit.cta_group::1.mbarrier::arrive::one.shared::cluster.multicast::cluster.b64 [%0], %1;"
        ::"r"(smem_u32(b)), "h"(mask) : "memory");
}
__device__ __forceinline__ void mbar_expect_tx(uint64_t* b, uint32_t bytes) {
    asm volatile("mbarrier.arrive.expect_tx.shared.b64 _, [%0], %1;"
                 ::"r"(smem_u32(b)), "r"(bytes) : "memory");
}
__device__ __forceinline__ void tma_2d(uint32_t smem, const CUtensorMap* tm,
                                       int c0, int c1, uint32_t mbar) {
    asm volatile(
        "cp.async.bulk.tensor.2d.shared::cta.global.tile.mbarrier::complete_tx::bytes "
        "[%0], [%1, {%2, %3}], [%4];"
        ::"r"(smem), "l"(tm), "r"(c0), "r"(c1), "r"(mbar) : "memory");
}
__device__ __forceinline__ void tma_2d_mc(uint32_t smem, const CUtensorMap* tm,
                                          int c0, int c1, uint32_t mbar,
                                          uint16_t mask) {
    asm volatile(
        "cp.async.bulk.tensor.2d.shared::cluster.global.tile.mbarrier::complete_tx::bytes.multicast::cluster "
        "[%0], [%1, {%2, %3}], [%4], %5;"
        ::"r"(smem), "l"(tm), "r"(c0), "r"(c1), "r"(mbar), "h"(mask) : "memory");
}
// SW128 K-major smem descriptor: layout=2, version=1, SBO=64, LBO=1
__device__ __forceinline__ uint64_t make_desc(uint32_t addr) {
    constexpr uint64_t BASE =
        (uint64_t(2) << 61) | (uint64_t(1) << 46) | (uint64_t(64) << 32) | (uint64_t(1) << 16);
    return BASE | ((uint64_t)(addr >> 4) & 0x3FFF);
}
__device__ __forceinline__ void mma_f16_ss(uint32_t d, uint64_t a, uint64_t b,
                                           uint32_t idesc, uint32_t en) {
    asm volatile(
        "{\n\t"
        ".reg .pred p;\n\t"
        "setp.ne.u32 p, %5, 0;\n\t"
        "tcgen05.mma.cta_group::1.kind::f16 [%0], %1, %2, %3, {%4, %4, %4, %4}, p;\n\t"
        "}"
        ::"r"(d), "l"(a), "l"(b), "r"(idesc), "r"(0u), "r"(en) : "memory");
}
__device__ __forceinline__ void tmem_ld_x32(uint32_t* r, uint32_t tmem_addr) {
    asm volatile(
        "tcgen05.ld.sync.aligned.32x32b.x32.b32 "
        "{%0, %1, %2, %3, %4, %5, %6, %7, "
        " %8, %9, %10, %11, %12, %13, %14, %15, "
        " %16, %17, %18, %19, %20, %21, %22, %23, "
        " %24, %25, %26, %27, %28, %29, %30, %31}, [%32];"
        : "=r"(r[0]), "=r"(r[1]), "=r"(r[2]), "=r"(r[3]),
          "=r"(r[4]), "=r"(r[5]), "=r"(r[6]), "=r"(r[7]),
          "=r"(r[8]), "=r"(r[9]), "=r"(r[10]), "=r"(r[11]),
          "=r"(r[12]), "=r"(r[13]), "=r"(r[14]), "=r"(r[15]),
          "=r"(r[16]), "=r"(r[17]), "=r"(r[18]), "=r"(r[19]),
          "=r"(r[20]), "=r"(r[21]), "=r"(r[22]), "=r"(r[23]),
          "=r"(r[24]), "=r"(r[25]), "=r"(r[26]), "=r"(r[27]),
          "=r"(r[28]), "=r"(r[29]), "=r"(r[30]), "=r"(r[31])
        : "r"(tmem_addr));
}
#endif  // HAS_TCGEN05

// ---------------------------------------------------------------------------
// Converters
// ---------------------------------------------------------------------------
__global__ void convert_x_kernel(const float4* __restrict__ x) {
    const size_t n4 = (size_t)B_SZ * F_DIM / 4;
    int2* out = reinterpret_cast<int2*>(g_xh);
    for (size_t i = (size_t)blockIdx.x * blockDim.x + threadIdx.x; i < n4;
         i += (size_t)gridDim.x * blockDim.x) {
        float4 v = __ldcs(x + i);
        __half2 h0 = __floats2half2_rn(v.x, v.y);
        __half2 h1 = __floats2half2_rn(v.z, v.w);
        int2 pk;
        pk.x = *reinterpret_cast<int*>(&h0);
        pk.y = *reinterpret_cast<int*>(&h1);
        __stcs(out + i, pk);
    }
}

// Coalesced tiled transpose: W[H][F][D] -> g_wqkv[n][f], n = which*1024+h*64+d.
__global__ void convert_wqkv_kernel(const float* __restrict__ Wq,
                                    const float* __restrict__ Wk,
                                    const float* __restrict__ Wv) {
    __shared__ float tile[32][33];
    const int which = blockIdx.z >> 4;
    const int h = blockIdx.z & 15;
    const int f0 = blockIdx.x * 32;
    const int d0 = blockIdx.y * 32;
    const float* W = (which == 0) ? Wq : ((which == 1) ? Wk : Wv);
    const float* src = W + ((size_t)h * F_DIM) * D_H;   // [F][D]

    const int tx = threadIdx.x;
    const int ty = threadIdx.y;
#pragma unroll
    for (int r = 0; r < 4; r++) {
        int f = f0 + ty + r * 8;
        int d = d0 + tx;
        if (d < D_H) tile[ty + r * 8][tx] = src[(size_t)f * D_H + d];
    }
    __syncthreads();
#pragma unroll
    for (int r = 0; r < 4; r++) {
        int d = d0 + ty + r * 8;
        int f = f0 + tx;
        if (d < D_H) {
            int n = which * 1024 + h * 64 + d;
            g_wqkv[(size_t)n * K_DIM + f] = __float2half(tile[tx][ty + r * 8]);
        }
    }
}

// Coalesced tiled transpose: Wf[K][N] -> g_wf[n][k].
__global__ void convert_wf_kernel(const float* __restrict__ Wf) {
    __shared__ float tile[32][33];
    const int k0 = blockIdx.x * 32;
    const int n0 = blockIdx.y * 32;
    const int tx = threadIdx.x;
    const int ty = threadIdx.y;
#pragma unroll
    for (int r = 0; r < 4; r++) {
        int k = k0 + ty + r * 8;
        tile[ty + r * 8][tx] = Wf[(size_t)k * OUT_N + n0 + tx];
    }
    __syncthreads();
#pragma unroll
    for (int r = 0; r < 4; r++) {
        int n = n0 + ty + r * 8;
        g_wf[(size_t)n * K_DIM + k0 + tx] = __float2half(tile[tx][ty + r * 8]);
    }
}

// ---------------------------------------------------------------------------
// Persistent tcgen05 GEMM, cluster-2 with B multicast, TMEM PING-PONG.
// Supertile 256M x 256N per cluster; rank r owns M rows [superM + 128r, +128).
// CTA tile M128 x N256 -> accumulator = 256 TMEM cols; two buffers (0/256)
// alternate per tile so the epilogue drain of tile i overlaps MMA of i+1.
// Stage (48KB): A own 16KB @0, B 32KB @16K (own mc half at +rank*16K).
// Epilogue warps 8-11 drain even tiles (buf0), 12-15 odd tiles (buf1).
// ---------------------------------------------------------------------------
#define STAGES 4
#define STAGE_BYTES 49152
#define SMEM_DYN (STAGES * STAGE_BYTES + 1024)
#define KT 16                      // 1024 / 64
#define NTHREADS 512               // 16 warps

// idesc: dtype=F32(1<<4), atype=btype=F16(0), N=256 -> 32<<17, M=128 -> 8<<24
#define IDESC_F16_N256 ((1u << 4) | (32u << 17) | (8u << 24))

template <int N_DIM, bool OUT_HALF, bool BIAS>
__global__ __launch_bounds__(NTHREADS, 1) __cluster_dims__(2, 1, 1)
void tc_gemm(const __grid_constant__ CUtensorMap tmA,
             const __grid_constant__ CUtensorMap tmB,
             const __half* __restrict__ A, const __half* __restrict__ Bw,
             __half* __restrict__ Ch, float* __restrict__ Cf,
             const float* __restrict__ bias, int numSuper, int superN) {
    extern __shared__ __align__(16) char dsm[];
    char* tiles = (char*)(((uintptr_t)dsm + 1023) & ~(uintptr_t)1023);

    const int tid = threadIdx.x;
    const int warp = tid >> 5;
    const int lane = tid & 31;
    const int C = gridDim.x >> 1;        // clusters
    const int cid = blockIdx.x >> 1;
    const int rank = (int)ctarank();     // 0 or 1 within cluster

#if HAS_TCGEN05
    __shared__ __align__(8) uint64_t bar_full[STAGES];
    __shared__ __align__(8) uint64_t bar_empty[STAGES];
    __shared__ __align__(8) uint64_t bar_done[2];
    __shared__ __align__(8) uint64_t bar_free[2];
    __shared__ uint32_t s_tmem;

    if (warp == 0) {
        asm volatile(
            "tcgen05.alloc.cta_group::1.sync.aligned.shared::cta.b32 [%0], %1;"
            ::"r"(smem_u32(&s_tmem)), "r"(512) : "memory");
    }
    if (tid == 0) {
        for (int s = 0; s < STAGES; s++) {
            mbar_init(&bar_full[s], 1);
            mbar_init(&bar_empty[s], 2);   // commits from BOTH cluster CTAs
        }
        mbar_init(&bar_done[0], 1);
        mbar_init(&bar_done[1], 1);
        mbar_init(&bar_free[0], 4);        // 4 epi warps per buffer group
        mbar_init(&bar_free[1], 4);
        asm volatile("fence.proxy.async.shared::cta;" ::: "memory");
    }
    __syncthreads();
    // All mbarriers must be cluster-visible before any multicast TMA / commit.
    asm volatile("barrier.cluster.arrive.aligned;" ::: "memory");
    asm volatile("barrier.cluster.wait.aligned;" ::: "memory");
    const uint32_t tmem = s_tmem;

    if (tid == 0) {
        // ------------------ producer: single thread, TMA ------------------
        asm volatile("prefetch.tensormap [%0];" ::"l"(&tmA));
        asm volatile("prefetch.tensormap [%0];" ::"l"(&tmB));
        int s = 0, ph = 1;  // fresh-barrier: parity-1 wait passes immediately
        for (int t = cid; t < numSuper; t += C) {
            const int tileM = (t / superN) * 256 + rank * 128;
            const int tileN = (t % superN) * 256;
            for (int kt = 0; kt < KT; kt++) {
                mbar_wait(&bar_empty[s], (uint32_t)ph);
                const uint32_t st = smem_u32(tiles + s * STAGE_BYTES);
                const uint32_t mb = smem_u32(&bar_full[s]);
                mbar_expect_tx(&bar_full[s], STAGE_BYTES);
                // own A M-half (unicast, own barrier)
                tma_2d(st, &tmA, kt * 64, tileM, mb);
                // one B box, multicast to both cluster CTAs
                tma_2d_mc(st + 16384 + rank * 16384, &tmB, kt * 64,
                          tileN + rank * 128, mb, (uint16_t)0x3);
                if (++s == STAGES) { s = 0; ph ^= 1; }
            }
        }
    } else if (warp == 4 && lane == 0) {
        // ------------------ MMA issue: single thread ------------------
        int s = 0, ph = 0, ti = 0;
        for (int t = cid; t < numSuper; t += C) {
            const int buf = ti & 1;
            const int u = ti >> 1;          // use-count of this buffer
            if (u >= 1) {
                // wait for epilogue group `buf` to free its accumulator
                mbar_wait(&bar_free[buf], (uint32_t)((u - 1) & 1));
                asm volatile("tcgen05.fence::after_thread_sync;" ::: "memory");
            }
            const uint32_t dacc = tmem + (uint32_t)buf * 256;
            for (int kt = 0; kt < KT; kt++) {
                mbar_wait(&bar_full[s], (uint32_t)ph);
                char* st = tiles + s * STAGE_BYTES;
                uint64_t a0 = make_desc(smem_u32(st));
                uint64_t b0 = make_desc(smem_u32(st + 16384));  // 256 rows
#pragma unroll
                for (int ks = 0; ks < 4; ks++) {
                    uint32_t en = (kt == 0 && ks == 0) ? 0u : 1u;
                    uint64_t ko = (uint64_t)(ks * 2);  // 32 bytes per K-step
                    mma_f16_ss(dacc, a0 + ko, b0 + ko, IDESC_F16_N256, en);
                }
                // release the stage in BOTH cluster CTAs (B box is shared)
                tc_commit_mc(&bar_empty[s], (uint16_t)0x3);
                if (++s == STAGES) { s = 0; ph ^= 1; }
            }
            tc_commit(&bar_done[buf]);
            ti++;
        }
    } else if (warp >= 8) {
        // --- epilogue: warps 8-11 -> buf 0 (even tiles), 12-15 -> buf 1 (odd).
        //     subp = warp&3 (TMEM subpartition HW map). M=128 rows per CTA. ---
        const int buf = (warp >> 2) - 2;           // 0 or 1
        const int subp = warp & 3;
        const uint32_t sacc = tmem + (uint32_t)buf * 256;
        int u = 0;
        for (int ti = buf;; ti += 2, u++) {
            const int t = cid + ti * C;
            if (t >= numSuper) break;
            const size_t tileM = (size_t)(t / superN) * 256 + rank * 128;
            const int tileN = (t % superN) * 256;
            mbar_wait(&bar_done[buf], (uint32_t)(u & 1));
            asm volatile("tcgen05.fence::after_thread_sync;" ::: "memory");
            const size_t grow = tileM + subp * 32 + lane;
#pragma unroll
            for (int nb = 0; nb < 8; nb += 2) {
                uint32_t r0[32], r1[32];
                tmem_ld_x32(r0, sacc + nb * 32);
                tmem_ld_x32(r1, sacc + nb * 32 + 32);
                asm volatile("tcgen05.wait::ld.sync.aligned;" ::: "memory");
#pragma unroll
                for (int half2i = 0; half2i < 2; half2i++) {
                    uint32_t* r = half2i ? r1 : r0;
                    const int gc0 = tileN + (nb + half2i) * 32;
                    if (OUT_HALF) {
                        __half2 h2[16];
#pragma unroll
                        for (int i = 0; i < 16; i++)
                            h2[i] = __floats2half2_rn(__uint_as_float(r[2 * i]),
                                                      __uint_as_float(r[2 * i + 1]));
                        int4* dst = reinterpret_cast<int4*>(Ch + grow * N_DIM + gc0);
#pragma unroll
                        for (int i = 0; i < 4; i++)
                            __stcs(dst + i, reinterpret_cast<int4*>(h2)[i]);
                    } else {
                        float4* dst = reinterpret_cast<float4*>(Cf + grow * N_DIM + gc0);
#pragma unroll
                        for (int i = 0; i < 8; i++) {
                            float4 v;
                            v.x = __uint_as_float(r[4 * i + 0]) + (BIAS ? bias[gc0 + 4 * i + 0] : 0.0f);
                            v.y = __uint_as_float(r[4 * i + 1]) + (BIAS ? bias[gc0 + 4 * i + 1] : 0.0f);
                            v.z = __uint_as_float(r[4 * i + 2]) + (BIAS ? bias[gc0 + 4 * i + 2] : 0.0f);
                            v.w = __uint_as_float(r[4 * i + 3]) + (BIAS ? bias[gc0 + 4 * i + 3] : 0.0f);
                            __stcs(dst + i, v);
                        }
                    }
                }
            }
            asm volatile("tcgen05.fence::before_thread_sync;" ::: "memory");
            if (lane == 0) mbar_arrive(&bar_free[buf]);
        }
    }

    __syncthreads();
    // No CTA may exit while another CTA's multicast could still target it.
    asm volatile("barrier.cluster.arrive.aligned;" ::: "memory");
    asm volatile("barrier.cluster.wait.aligned;" ::: "memory");
    if (warp == 0) {
        asm volatile("tcgen05.relinquish_alloc_permit.cta_group::1.sync.aligned;");
        asm volatile("tcgen05.dealloc.cta_group::1.sync.aligned.b32 %0, %1;"
                     ::"r"(tmem), "r"(512));
    }

#else  // ----------------- fallback: wmma, persistent over tiles -----------------
    using namespace nvcuda;
    constexpr int BK = 32;
    constexpr int LDAf = BK + 8;   // 40

    __half (*As)[128][LDAf] = reinterpret_cast<__half (*)[128][LDAf]>(tiles);
    __half (*Bk)[128][LDAf] = reinterpret_cast<__half (*)[128][LDAf]>(tiles + 2 * 128 * LDAf * 2);
    float (*stg)[256]       = reinterpret_cast<float (*)[256]>(tiles + 4 * 128 * LDAf * 2);

    const int wm = (warp >> 2) & 1;
    const int wn = warp & 3;

    for (int t = cid; t < numSuper; t += C) {
        const size_t tM = (size_t)(t / superN) * 256 + (size_t)rank * 128;
        const int tileN0 = (t % superN) * 256;
        for (int ni = 0; ni < 2; ni++) {
            const int tN = tileN0 + ni * 128;

            wmma::fragment<wmma::accumulator, 16, 16, 16, float> acc[2][2];
#pragma unroll
            for (int i = 0; i < 2; i++)
#pragma unroll
                for (int jj = 0; jj < 2; jj++) wmma::fill_fragment(acc[i][jj], 0.0f);

            auto loadTiles2 = [&](int buf, int k0) {
                for (int c = tid; c < 512; c += NTHREADS) {
                    int row = c >> 2, seg = c & 3;
                    cp_async16(smem_u32(&As[buf][row][seg * 8]),
                               A + (tM + row) * K_DIM + k0 + seg * 8);
                }
                for (int c = tid; c < 512; c += NTHREADS) {
                    int row = c >> 2, seg = c & 3;
                    cp_async16(smem_u32(&Bk[buf][row][seg * 8]),
                               Bw + (size_t)(tN + row) * K_DIM + k0 + seg * 8);
                }
                asm volatile("cp.async.commit_group;\n");
            };

            loadTiles2(0, 0);
            constexpr int KT2 = K_DIM / BK;  // 32
            for (int kt = 0; kt < KT2; ++kt) {
                if (kt + 1 < KT2)
                    loadTiles2((kt + 1) & 1, (kt + 1) * BK);
                else
                    asm volatile("cp.async.commit_group;\n");
                asm volatile("cp.async.wait_group 1;\n");
                __syncthreads();

                const int buf = kt & 1;
                if (warp < 8) {
#pragma unroll
                    for (int kk = 0; kk < BK; kk += 16) {
                        wmma::fragment<wmma::matrix_a, 16, 16, 16, __half, wmma::row_major> af[2];
                        wmma::fragment<wmma::matrix_b, 16, 16, 16, __half, wmma::col_major> bfr[2];
#pragma unroll
                        for (int i = 0; i < 2; i++)
                            wmma::load_matrix_sync(af[i], &As[buf][wm * 64 + i * 16 + 32][kk], LDAf);
#pragma unroll
                        for (int jj = 0; jj < 2; jj++)
                            wmma::load_matrix_sync(bfr[jj], &Bk[buf][wn * 32 + jj * 16][kk], LDAf);
#pragma unroll
                        for (int i = 0; i < 2; i++)
#pragma unroll
                            for (int jj = 0; jj < 2; jj++)
                                wmma::mma_sync(acc[i][jj], af[i], bfr[jj], acc[i][jj]);
                    }
                }
                __syncthreads();
            }

            if (warp < 8) {
#pragma unroll
                for (int i = 0; i < 2; i++) {
#pragma unroll
                    for (int jj = 0; jj < 2; jj++) {
                        wmma::store_matrix_sync(stg[warp], acc[i][jj], 16, wmma::mem_row_major);
                        __syncwarp();
#pragma unroll
                        for (int p = 0; p < 8; p++) {
                            int e = lane + p * 32;
                            int r2 = e >> 4, cc = e & 15;
                            size_t grow2 = tM + wm * 64 + i * 16 + 32 + r2;
                            int gcol = tN + wn * 32 + jj * 16 + cc;
                            float v = stg[warp][e];
                            if (BIAS) v += bias[gcol];
                            if (OUT_HALF)
                                Ch[grow2 * N_DIM + gcol] = __float2half(v);
                            else
                                Cf[grow2 * N_DIM + gcol] = v;
                        }
                        __syncwarp();
                    }
                }
            }
            __syncthreads();
        }
    }
#endif
}

// ---------------------------------------------------------------------------
// Pipelined tensor-core attention. One warp per row; 2-deep cp.async double
// buffering hides the 6KB row fetch behind the previous row's compute.
// ---------------------------------------------------------------------------
#define AT_WARPS 8
#define AT_WB 13824
#define AT_SMEM (AT_WARPS * AT_WB)

__global__ __launch_bounds__(AT_WARPS * 32) void attn_kernel(int nwtot) {
    using namespace nvcuda;
    extern __shared__ __align__(16) char ats[];

    const int w = threadIdx.x >> 5;
    const int L = threadIdx.x & 31;
    char* wb = ats + w * AT_WB;
    __half* bufs[2] = {reinterpret_cast<__half*>(wb),
                       reinterpret_cast<__half*>(wb + 6144)};
    __half* wgt = reinterpret_cast<__half*>(wb + 12288);
    float*  ssc = reinterpret_cast<float*>(wb + 12800);

    const int gw = blockIdx.x * AT_WARPS + w;

    auto prefetch = [&](int bi, size_t row) {
        const char* src = reinterpret_cast<const char*>(g_qkv + row * NQKV);
        uint32_t d = smem_u32(bufs[bi]);
#pragma unroll
        for (int i = 0; i < 12; i++)
            cp_async16(d + (uint32_t)(L + i * 32) * 16, src + (size_t)(L + i * 32) * 16);
    };

    size_t row = (size_t)gw;
    if (row < B_SZ) prefetch(0, row);
    asm volatile("cp.async.commit_group;\n");

    int cur = 0;
    for (; row < B_SZ; row += (size_t)nwtot) {
        const size_t nrow = row + (size_t)nwtot;
        if (nrow < B_SZ) prefetch(cur ^ 1, nrow);
        asm volatile("cp.async.commit_group;\n");
        asm volatile("cp.async.wait_group 1;\n");
        __syncwarp();

        __half* sqkv = bufs[cur];
        float* so = reinterpret_cast<float*>(sqkv);   // overlays q,k (dead after frags)

        // QK^T: scores[h][g]
        {
            wmma::fragment<wmma::accumulator, 16, 16, 16, float> sacc;
            wmma::fill_fragment(sacc, 0.0f);
#pragma unroll
            for (int kc = 0; kc < 4; kc++) {
                wmma::fragment<wmma::matrix_a, 16, 16, 16, __half, wmma::row_major> qa;
                wmma::fragment<wmma::matrix_b, 16, 16, 16, __half, wmma::col_major> kb;
                wmma::load_matrix_sync(qa, sqkv + kc * 16, 64);
                wmma::load_matrix_sync(kb, sqkv + 1024 + kc * 16, 64);
                wmma::mma_sync(sacc, qa, kb, sacc);
            }
            wmma::store_matrix_sync(ssc, sacc, 16, wmma::mem_row_major);
        }
        __syncwarp();

        // softmax rows (lanes 0-15), fp16 weights
        if (L < 16) {
            float r[16];
            float m = -1e30f;
#pragma unroll
            for (int g = 0; g < 16; g++) {
                r[g] = ssc[L * 16 + g] * 0.125f;
                m = fmaxf(m, r[g]);
            }
            float sum = 0.0f;
#pragma unroll
            for (int g = 0; g < 16; g++) {
                r[g] = __expf(r[g] - m);
                sum += r[g];
            }
            float inv = 1.0f / sum;
#pragma unroll
            for (int g = 0; g < 16; g++)
                wgt[L * 16 + g] = __float2half(r[g] * inv);
        }
        __syncwarp();

        // AV: o[h][d] = sum_g w[h][g] * v[g][d]
        {
            wmma::fragment<wmma::matrix_a, 16, 16, 16, __half, wmma::row_major> wa;
            wmma::load_matrix_sync(wa, wgt, 16);
            wmma::fragment<wmma::matrix_b, 16, 16, 16, __half, wmma::row_major> vb[4];
#pragma unroll
            for (int dc = 0; dc < 4; dc++)
                wmma::load_matrix_sync(vb[dc], sqkv + 2048 + dc * 16, 64);
            __syncwarp();   // v frags in regs before o overlays q,k
            wmma::fragment<wmma::accumulator, 16, 16, 16, float> oacc;
#pragma unroll
            for (int dc = 0; dc < 4; dc++) {
                wmma::fill_fragment(oacc, 0.0f);
                wmma::mma_sync(oacc, wa, vb[dc], oacc);
                wmma::store_matrix_sync(so + dc * 16, oacc, 64, wmma::mem_row_major);
            }
        }
        __syncwarp();

        // transposed write: c[d*16+h]; lane L -> 32 contiguous halves (4x16B)
        __half hbuf[32];
#pragma unroll
        for (int i = 0; i < 16; i++) hbuf[i] = __float2half(so[i * 64 + 2 * L]);
#pragma unroll
        for (int i = 0; i < 16; i++) hbuf[16 + i] = __float2half(so[i * 64 + 2 * L + 1]);
        int4* co = reinterpret_cast<int4*>(g_c + row * F_DIM + 32 * L);
#pragma unroll
        for (int i = 0; i < 4; i++) __stcs(co + i, reinterpret_cast<int4*>(hbuf)[i]);
        __syncwarp();   // so reads done before next iteration's prefetch reuse

        cur ^= 1;
    }
}

// ---------------------------------------------------------------------------
// Host: tensor-map encode via driver entry point (no -lcuda link dependency)
// ---------------------------------------------------------------------------
typedef CUresult (*EncodeTiledFn)(
    CUtensorMap*, CUtensorMapDataType, cuuint32_t, void*,
    const cuuint64_t*, const cuuint64_t*, const cuuint32_t*, const cuuint32_t*,
    CUtensorMapInterleave, CUtensorMapSwizzle, CUtensorMapL2promotion,
    CUtensorMapFloatOOBfill);

static void encode_tm_2d(EncodeTiledFn fn, CUtensorMap* tm, void* base,
                         unsigned long long rows) {
    cuuint64_t dims[2]    = {(cuuint64_t)K_DIM, (cuuint64_t)rows};
    cuuint64_t strides[1] = {(cuuint64_t)K_DIM * 2};
    cuuint32_t box[2]     = {64, 128};
    cuuint32_t es[2]      = {1, 1};
    fn(tm, CU_TENSOR_MAP_DATA_TYPE_FLOAT16, 2, base, dims, strides, box, es,
       CU_TENSOR_MAP_INTERLEAVE_NONE, CU_TENSOR_MAP_SWIZZLE_128B,
       CU_TENSOR_MAP_L2_PROMOTION_L2_128B, CU_TENSOR_MAP_FLOAT_OOB_FILL_NONE);
}

extern "C" void kernel_launch(void* const* d_in, const int* in_sizes, int n_in,
                              void* d_out, int out_size) {
    const float* x  = (const float*)d_in[0];
    const float* Wq = (const float*)d_in[1];
    const float* Wk = (const float*)d_in[2];
    const float* Wv = (const float*)d_in[3];
    const float* Wf = (const float*)d_in[4];
    const float* bf = (const float*)d_in[5];
    float* out = (float*)d_out;

    void *p_xh = nullptr, *p_wqkv = nullptr, *p_wf = nullptr, *p_qkv = nullptr,
         *p_c = nullptr;
    cudaGetSymbolAddress(&p_xh, g_xh);
    cudaGetSymbolAddress(&p_wqkv, g_wqkv);
    cudaGetSymbolAddress(&p_wf, g_wf);
    cudaGetSymbolAddress(&p_qkv, g_qkv);
    cudaGetSymbolAddress(&p_c, g_c);

    EncodeTiledFn enc = nullptr;
    cudaDriverEntryPointQueryResult qr;
    cudaGetDriverEntryPoint("cuTensorMapEncodeTiled", (void**)&enc,
                            cudaEnableDefault, &qr);

    CUtensorMap tmA1{}, tmB1{}, tmA2{}, tmB2{};
    encode_tm_2d(enc, &tmA1, p_xh, B_SZ);     // GEMM1 A: x fp16 [65536,1024]
    encode_tm_2d(enc, &tmB1, p_wqkv, NQKV);   // GEMM1 B: Wqkv^T [3072,1024]
    encode_tm_2d(enc, &tmA2, p_c, B_SZ);      // GEMM2 A: concat [65536,1024]
    encode_tm_2d(enc, &tmB2, p_wf, OUT_N);    // GEMM2 B: Wf^T [1024,1024]

    int nsm = 148;
    cudaDeviceGetAttribute(&nsm, cudaDevAttrMultiProcessorCount, 0);
    int grid = nsm & ~1;   // even: cluster size 2

    cudaFuncSetAttribute(tc_gemm<NQKV, true, false>,
                         cudaFuncAttributeMaxDynamicSharedMemorySize, SMEM_DYN);
    cudaFuncSetAttribute(tc_gemm<OUT_N, false, true>,
                         cudaFuncAttributeMaxDynamicSharedMemorySize, SMEM_DYN);
    cudaFuncSetAttribute(attn_kernel,
                         cudaFuncAttributeMaxDynamicSharedMemorySize, AT_SMEM);

    convert_x_kernel<<<16384, 256>>>(reinterpret_cast<const float4*>(x));
    convert_wqkv_kernel<<<dim3(32, 2, 48), dim3(32, 8)>>>(Wq, Wk, Wv);
    convert_wf_kernel<<<dim3(32, 32), dim3(32, 8)>>>(Wf);

    // QKV = x @ Wqkv^T   (3072 supertiles of 256x256 per cluster)
    tc_gemm<NQKV, true, false><<<grid, NTHREADS, SMEM_DYN>>>(
        tmA1, tmB1, (const __half*)p_xh, (const __half*)p_wqkv,
        (__half*)p_qkv, nullptr, nullptr,
        (B_SZ / 256) * (NQKV / 256), NQKV / 256);

    // attention over heads -> transposed concat (pipelined tensor-core path)
    int ablocks = 2 * nsm;
    attn_kernel<<<ablocks, AT_WARPS * 32, AT_SMEM>>>(ablocks * AT_WARPS);

    // out = concat @ Wf^T + bf   (1024 supertiles)
    tc_gemm<OUT_N, false, true><<<grid, NTHREADS, SMEM_DYN>>>(
        tmA2, tmB2, (const __half*)p_c, (const __half*)p_wf,
        nullptr, out, bf,
        (B_SZ / 256) * (OUT_N / 256), OUT_N / 256);
}